// round 5
// baseline (speedup 1.0000x reference)
#include <cuda_runtime.h>
#include <math.h>

#define NNODE 20000
#define NEDGE 160000
#define E2    320000
#define HH    128
#define NF    16
#define EF    16

// ---------------- device scratch (no allocations allowed) ----------------
__device__ int   g_deg[NNODE];
__device__ int   g_rowoff[NNODE];
__device__ int   g_cursor[NNODE];
__device__ float g_dis[NNODE];
__device__ int   g_csr_src[E2];
__device__ int   g_csr_ea[E2];                 // eattr index (0..NEDGE)
__device__ float g_h0[NNODE * NF];
__device__ float g_nb[5][NNODE * HH];          // node-feature buffers
__device__ float g_msg[(size_t)NEDGE * HH];    // per-unique-edge C buffer (82 MB)

__device__ __forceinline__ const float* sel_in(int s, const float* ext) {
    if (s >= 0) return g_nb[s];
    if (s == -3) return g_h0;
    return ext;
}

// ---------------- packed fp32x2 helpers (Blackwell FFMA2) ----------------
__device__ __forceinline__ unsigned long long pk2(float a, float b) {
    unsigned long long r;
    asm("mov.b64 %0, {%1, %2};" : "=l"(r) : "f"(a), "f"(b));
    return r;
}
__device__ __forceinline__ void fma2(unsigned long long& d,
                                     unsigned long long a, unsigned long long b) {
    asm("fma.rn.f32x2 %0, %1, %2, %0;" : "+l"(d) : "l"(a), "l"(b));
}
__device__ __forceinline__ float hadd2(unsigned long long v) {
    float lo, hi;
    asm("mov.b64 {%0, %1}, %2;" : "=f"(lo), "=f"(hi) : "l"(v));
    return lo + hi;
}

// ---------------- graph structure build ----------------
__global__ void k_zero() {
    int i = blockIdx.x * 256 + threadIdx.x;
    if (i < NNODE) g_deg[i] = 0;
}

__global__ void k_hist(const int* __restrict__ ei) {
    int e = blockIdx.x * 256 + threadIdx.x;
    if (e >= E2) return;
    int d = (e < NEDGE) ? ei[NEDGE + e] : ei[e - NEDGE];
    atomicAdd(&g_deg[d], 1);
}

// warp-shuffle block scan (single block, 1024 threads, 20 elems/thread)
__global__ void k_scan() {
    __shared__ int wsum[32];
    int t = threadIdx.x, lane = t & 31, wid = t >> 5;
    const int PER = 20;                       // 1024*20 = 20480 >= NNODE
    int base = t * PER;
    int s = 0;
#pragma unroll
    for (int i = 0; i < PER; i++) { int idx = base + i; if (idx < NNODE) s += g_deg[idx]; }
    int x = s;
#pragma unroll
    for (int off = 1; off < 32; off <<= 1) {
        int y = __shfl_up_sync(0xffffffffu, x, off);
        if (lane >= off) x += y;
    }
    if (lane == 31) wsum[wid] = x;
    __syncthreads();
    if (wid == 0) {
        int y = wsum[lane];
#pragma unroll
        for (int off = 1; off < 32; off <<= 1) {
            int z = __shfl_up_sync(0xffffffffu, y, off);
            if (lane >= off) y += z;
        }
        wsum[lane] = y;
    }
    __syncthreads();
    int run = x - s + (wid > 0 ? wsum[wid - 1] : 0);
#pragma unroll
    for (int i = 0; i < PER; i++) {
        int idx = base + i;
        if (idx < NNODE) {
            int v = g_deg[idx];
            g_rowoff[idx] = run;
            g_cursor[idx] = run;
            g_dis[idx] = (v > 0) ? rsqrtf((float)v) : 0.f;
            run += v;
        }
    }
}

__global__ void k_scatter(const int* __restrict__ ei) {
    int e = blockIdx.x * 256 + threadIdx.x;
    if (e >= E2) return;
    int srcv = ei[e];  // both halves: [0,E)=src row, [E,2E)=dst row reversed
    int d  = (e < NEDGE) ? ei[NEDGE + e] : ei[e - NEDGE];
    int ea = (e < NEDGE) ? e : e - NEDGE;
    int slot = atomicAdd(&g_cursor[d], 1);
    g_csr_src[slot] = srcv;
    g_csr_ea[slot]  = ea;
}

// ---------------- mask MLP + residual: g_h0 = mlp2(mask) + x ----------------
__global__ void __launch_bounds__(128) k_maskmlp(
    const float* __restrict__ x, const float* __restrict__ mask,
    const float* __restrict__ w1, const float* __restrict__ b1,
    const float* __restrict__ w2, const float* __restrict__ b2)
{
    constexpr int T = 16;
    __shared__ __align__(16) float sM[T * NF];
    __shared__ __align__(16) float sH[T * HH];
    int tid = threadIdx.x;
    int n0 = blockIdx.x * T;
    for (int o = tid; o < T * NF; o += 128) sM[o] = mask[n0 * NF + o];
    __syncthreads();

    float acc[T];
    float bj = b1[tid];
#pragma unroll
    for (int t = 0; t < T; t++) acc[t] = bj;
#pragma unroll
    for (int i = 0; i < NF; i += 4) {
        float wa = w1[(i + 0) * HH + tid], wb = w1[(i + 1) * HH + tid];
        float wc = w1[(i + 2) * HH + tid], wd = w1[(i + 3) * HH + tid];
#pragma unroll
        for (int t = 0; t < T; t++) {
            float4 v = *reinterpret_cast<const float4*>(&sM[t * NF + i]);
            acc[t] = fmaf(v.x, wa, acc[t]); acc[t] = fmaf(v.y, wb, acc[t]);
            acc[t] = fmaf(v.z, wc, acc[t]); acc[t] = fmaf(v.w, wd, acc[t]);
        }
    }
#pragma unroll
    for (int t = 0; t < T; t++) sH[t * HH + tid] = fmaxf(acc[t], 0.f);
    __syncthreads();

    for (int o = tid; o < T * NF; o += 128) {
        int t = o >> 4, c = o & 15;
        float v = b2[c];
#pragma unroll 1
        for (int k = 0; k < HH; k += 4) {
            float4 h = *reinterpret_cast<const float4*>(&sH[t * HH + k]);
            v = fmaf(h.x, w2[(k + 0) * NF + c], v);
            v = fmaf(h.y, w2[(k + 1) * NF + c], v);
            v = fmaf(h.z, w2[(k + 2) * NF + c], v);
            v = fmaf(h.w, w2[(k + 3) * NF + c], v);
        }
        g_h0[n0 * NF + o] = v + x[n0 * NF + o];
    }
}

// ---------------- GEMM: out[M,128] = op(in[M,K] @ W[K,128])  (packed f32x2) ----
// BIASMODE: 0 = none, 1 = +bias, 2 = +deg[n]*bias. ACCUM: out += result.
template <int K, int BIASMODE, bool RELU, bool ACCUM>
__global__ void __launch_bounds__(128) k_mm(
    int insel, const float* __restrict__ in_ext,
    float* __restrict__ outp,
    const float* __restrict__ W, const float* __restrict__ bias)
{
    constexpr int T = 16;
    __shared__ __align__(16) float sIn[T * K];
    const float* in = sel_in(insel, in_ext);
    int tid = threadIdx.x;
    int j = tid;
    int n0 = blockIdx.x * T;

    const float4* gsrc = reinterpret_cast<const float4*>(in + (size_t)n0 * K);
    float4* ssrc = reinterpret_cast<float4*>(sIn);
    for (int o = tid; o < T * K / 4; o += 128) ssrc[o] = gsrc[o];
    __syncthreads();

    unsigned long long acc2[T];
#pragma unroll
    for (int t = 0; t < T; t++) acc2[t] = 0ULL;

#pragma unroll 1
    for (int k = 0; k < K; k += 4) {
        float wa = W[(k + 0) * HH + j], wb = W[(k + 1) * HH + j];
        float wc = W[(k + 2) * HH + j], wd = W[(k + 3) * HH + j];
        unsigned long long w01 = pk2(wa, wb), w23 = pk2(wc, wd);
#pragma unroll
        for (int t = 0; t < T; t++) {
            ulonglong2 q = *reinterpret_cast<const ulonglong2*>(&sIn[t * K + k]);
            fma2(acc2[t], q.x, w01);
            fma2(acc2[t], q.y, w23);
        }
    }

    float binit = 0.f;
    if (BIASMODE == 1) binit = bias[j];
    float bscale = (BIASMODE == 2) ? bias[j] : 0.f;
#pragma unroll
    for (int t = 0; t < T; t++) {
        float v = hadd2(acc2[t]) + binit;
        if (BIASMODE == 2) v += bscale * (float)g_deg[n0 + t];
        if (ACCUM) v += outp[(size_t)(n0 + t) * HH + j];
        if (RELU) v = fmaxf(v, 0.f);
        outp[(size_t)(n0 + t) * HH + j] = v;
    }
}

// ---------------- twin GEMM: nb0 = in@WA + biasA ; nb1 = in@WB  (shared input) ----
template <int K>
__global__ void __launch_bounds__(256) k_mmAB(
    int insel, const float* __restrict__ in_ext,
    const float* __restrict__ WA, const float* __restrict__ biasA,
    const float* __restrict__ WB)
{
    constexpr int T = 16;
    __shared__ __align__(16) float sIn[T * K];
    const float* in = sel_in(insel, in_ext);
    int tid = threadIdx.x;
    int j = tid & 127;
    bool isA = tid < 128;
    const float* W = isA ? WA : WB;
    float* out = isA ? g_nb[0] : g_nb[1];
    int n0 = blockIdx.x * T;

    const float4* gsrc = reinterpret_cast<const float4*>(in + (size_t)n0 * K);
    float4* ssrc = reinterpret_cast<float4*>(sIn);
    for (int o = tid; o < T * K / 4; o += 256) ssrc[o] = gsrc[o];
    __syncthreads();

    unsigned long long acc2[T];
#pragma unroll
    for (int t = 0; t < T; t++) acc2[t] = 0ULL;

#pragma unroll 1
    for (int k = 0; k < K; k += 4) {
        float wa = W[(k + 0) * HH + j], wb = W[(k + 1) * HH + j];
        float wc = W[(k + 2) * HH + j], wd = W[(k + 3) * HH + j];
        unsigned long long w01 = pk2(wa, wb), w23 = pk2(wc, wd);
#pragma unroll
        for (int t = 0; t < T; t++) {
            ulonglong2 q = *reinterpret_cast<const ulonglong2*>(&sIn[t * K + k]);
            fma2(acc2[t], q.x, w01);
            fma2(acc2[t], q.y, w23);
        }
    }

    float b = isA ? biasA[j] : 0.f;
#pragma unroll
    for (int t = 0; t < T; t++)
        out[(size_t)(n0 + t) * HH + j] = hadd2(acc2[t]) + b;
}

// ---------------- fused hidden + aggregation ----------------
// S[n] = sum over incident edges of relu(A[n] + B[src] + C[ea])
__global__ void k_fused_agg() {
    const float* __restrict__ A = g_nb[0];
    const float* __restrict__ B = g_nb[1];
    float* __restrict__ S = g_nb[2];
    int n = blockIdx.x, j = threadIdx.x;
    int beg = g_rowoff[n], len = g_deg[n];
    float a = A[n * HH + j];
    float acc = 0.f;
    for (int i = 0; i < len; i++) {
        int s  = __ldg(&g_csr_src[beg + i]);
        int ea = __ldg(&g_csr_ea[beg + i]);
        acc += fmaxf(a + __ldg(&B[s * HH + j]) + __ldg(&g_msg[(size_t)ea * HH + j]), 0.f);
    }
    S[n * HH + j] = acc;
}

// ---------------- TAG propagation hop: out[n] = dis[n] * sum dis[s] * h[s] ----------------
__global__ void k_hop(int insel, int outsel) {
    const float* __restrict__ hin = g_nb[insel];
    float* __restrict__ hout = g_nb[outsel];
    int n = blockIdx.x, j = threadIdx.x;
    int beg = g_rowoff[n], len = g_deg[n];
    float acc = 0.f;
    for (int i = 0; i < len; i++) {
        int s = __ldg(&g_csr_src[beg + i]);
        acc = fmaf(__ldg(&g_dis[s]), __ldg(&hin[s * HH + j]), acc);
    }
    hout[n * HH + j] = g_dis[n] * acc;
}

// ---------------- final: out[n,16] = S[n]@W2[128,16] + deg[n]*b2 ----------------
__global__ void __launch_bounds__(128) k_out16(
    float* __restrict__ out, const float* __restrict__ W2, const float* __restrict__ b2)
{
    int tid = threadIdx.x;
    int n = blockIdx.x * 8 + (tid >> 4);
    int c = tid & 15;
    const float* S = g_nb[2];
    float acc = b2[c] * (float)g_deg[n];
#pragma unroll 4
    for (int k = 0; k < HH; k++)
        acc = fmaf(__ldg(&S[n * HH + k]), __ldg(&W2[k * 16 + c]), acc);
    out[n * 16 + c] = acc;
}

// ---------------- launch ----------------
extern "C" void kernel_launch(void* const* d_in, const int* in_sizes, int n_in,
                              void* d_out, int out_size)
{
    static const int ESZ[24] = {
        320000, 320000, 2560000, 320000,
        2048, 128, 2048, 16,
        6144, 128, 16384, 128,
        65536, 128,
        34816, 128, 16384, 128,
        65536, 128,
        34816, 128, 2048, 16};
    static const int M_DICT[24] = {0,1,2,3,4,5,6,7,8,9,10,11,12,13,14,15,16,17,18,19,20,21,22,23};
    static const int M_SIG[24]  = {0,1,2,23,3,4,5,6,7,8,9,10,11,12,13,14,15,16,17,18,19,20,21,22};
    static const int M_ALPHA[24]= {23,18,12,13,16,14,17,15,2,0,3,1,20,19,6,4,7,5,22,21,10,8,11,9};
    const int* cands[3] = {M_DICT, M_SIG, M_ALPHA};
    const int* map = M_DICT;
    for (int ci = 0; ci < 3; ci++) {
        bool ok = (n_in >= 24);
        for (int l = 0; l < 24 && ok; l++) ok = (in_sizes[cands[ci][l]] == ESZ[l]);
        if (ok) { map = cands[ci]; break; }
    }
#define INP(l) ((const float*)d_in[map[l]])
    const float* x     = INP(0);
    const float* mask  = INP(1);
    const float* eattr = INP(2);
    const int*   ei    = (const int*)d_in[map[3]];
    const float *m_w1 = INP(4), *m_b1 = INP(5), *m_w2 = INP(6), *m_b2 = INP(7);
    const float *ea0w1 = INP(8), *ea0b1 = INP(9), *ea0w2 = INP(10), *ea0b2 = INP(11);
    const float *tag0w = INP(12), *tag0b = INP(13);
    const float *ea1w1 = INP(14), *ea1b1 = INP(15), *ea1w2 = INP(16), *ea1b2 = INP(17);
    const float *tag1w = INP(18), *tag1b = INP(19);
    const float *ea2w1 = INP(20), *ea2b1 = INP(21), *ea2w2 = INP(22), *ea2b2 = INP(23);
#undef INP
    float* out = (float*)d_out;
    (void)out_size;

    const int GN = NNODE / 16;   // 1250 node-GEMM blocks
    const int GE = NEDGE / 16;   // 10000 edge-C blocks

    float* nb0 = nullptr; // selectors used instead; outp passed explicitly below
    (void)nb0;

    // device buffer addresses for explicit outp (resolved via a tiny launch-side trick:
    // k_mm takes outp pointer; we can't take g_nb address on host, so pass via insel-style
    // wrappers). Simplest: use cudaGetSymbolAddress once -- but that is NOT graph-capture
    // hostile and allocates nothing. It is a pure address query.
    static float* s_nb[5] = {nullptr, nullptr, nullptr, nullptr, nullptr};
    static float* s_msg = nullptr;
    if (!s_nb[0]) {
        void* p = nullptr;
        cudaGetSymbolAddress(&p, g_nb);
        for (int i = 0; i < 5; i++) s_nb[i] = (float*)p + (size_t)i * NNODE * HH;
        cudaGetSymbolAddress(&p, g_msg);
        s_msg = (float*)p;
    }

    // graph structure
    k_zero<<<(NNODE + 255) / 256, 256>>>();
    k_hist<<<E2 / 256, 256>>>(ei);
    k_scan<<<1, 1024>>>();
    k_scatter<<<E2 / 256, 256>>>(ei);

    // node embedding
    k_maskmlp<<<GN, 128>>>(x, mask, m_w1, m_b1, m_w2, m_b2);

    // ---- EA0 (h0[16] -> 128): A,B twin GEMM; C edge GEMM; agg; layer-2 ----
    k_mmAB<16><<<GN, 256>>>(-3, nullptr, ea0w1, ea0b1, ea0w1 + 16 * HH);
    k_mm<16, 0, false, false><<<GE, 128>>>(-1, eattr, s_msg, ea0w1 + 32 * HH, nullptr);
    k_fused_agg<<<NNODE, 128>>>();
    k_mm<128, 2, true, false><<<GN, 128>>>(2, nullptr, s_nb[3], ea0w2, ea0b2);

    // ---- TAG0: in nb3 -> out nb4 (relu), tmps nb0/nb1 ----
    k_mm<128, 1, false, false><<<GN, 128>>>(3, nullptr, s_nb[4], tag0w,               tag0b);
    k_hop<<<NNODE, 128>>>(3, 0);
    k_mm<128, 0, false, true ><<<GN, 128>>>(0, nullptr, s_nb[4], tag0w + 1 * HH * HH, nullptr);
    k_hop<<<NNODE, 128>>>(0, 1);
    k_mm<128, 0, false, true ><<<GN, 128>>>(1, nullptr, s_nb[4], tag0w + 2 * HH * HH, nullptr);
    k_hop<<<NNODE, 128>>>(1, 0);
    k_mm<128, 0, true,  true ><<<GN, 128>>>(0, nullptr, s_nb[4], tag0w + 3 * HH * HH, nullptr);

    // ---- EA1 (nb4 -> 128) ----
    k_mmAB<128><<<GN, 256>>>(4, nullptr, ea1w1, ea1b1, ea1w1 + 128 * HH);
    k_mm<16, 0, false, false><<<GE, 128>>>(-1, eattr, s_msg, ea1w1 + 256 * HH, nullptr);
    k_fused_agg<<<NNODE, 128>>>();
    k_mm<128, 2, true, false><<<GN, 128>>>(2, nullptr, s_nb[3], ea1w2, ea1b2);

    // ---- TAG1: in nb3 -> out nb4 (relu) ----
    k_mm<128, 1, false, false><<<GN, 128>>>(3, nullptr, s_nb[4], tag1w,               tag1b);
    k_hop<<<NNODE, 128>>>(3, 0);
    k_mm<128, 0, false, true ><<<GN, 128>>>(0, nullptr, s_nb[4], tag1w + 1 * HH * HH, nullptr);
    k_hop<<<NNODE, 128>>>(0, 1);
    k_mm<128, 0, false, true ><<<GN, 128>>>(1, nullptr, s_nb[4], tag1w + 2 * HH * HH, nullptr);
    k_hop<<<NNODE, 128>>>(1, 0);
    k_mm<128, 0, true,  true ><<<GN, 128>>>(0, nullptr, s_nb[4], tag1w + 3 * HH * HH, nullptr);

    // ---- EA2 (nb4 -> 16) -> d_out ----
    k_mmAB<128><<<GN, 256>>>(4, nullptr, ea2w1, ea2b1, ea2w1 + 128 * HH);
    k_mm<16, 0, false, false><<<GE, 128>>>(-1, eattr, s_msg, ea2w1 + 256 * HH, nullptr);
    k_fused_agg<<<NNODE, 128>>>();
    k_out16<<<NNODE / 8, 128>>>(out, ea2w2, ea2b2);
}

// round 6
// speedup vs baseline: 1.0326x; 1.0326x over previous
#include <cuda_runtime.h>
#include <math.h>

#define NNODE 20000
#define NEDGE 160000
#define E2    320000
#define HH    128
#define NF    16
#define EF    16

// ---------------- device scratch (no allocations allowed) ----------------
__device__ int   g_deg[NNODE];
__device__ int   g_rowoff[NNODE];
__device__ int   g_cursor[NNODE];
__device__ float g_dis[NNODE];
__device__ int   g_csr_src[E2];
__device__ int   g_csr_ea[E2];                 // eattr index (0..NEDGE)
__device__ float g_h0[NNODE * NF];
__device__ float g_nb[5][NNODE * HH];          // node-feature buffers
__device__ float g_msg[3][(size_t)NEDGE * HH]; // per-unique-edge C buffers (3 x 82 MB)

__device__ __forceinline__ const float* sel_in(int s, const float* ext) {
    if (s >= 0) return g_nb[s];
    if (s == -3) return g_h0;
    return ext;
}

// ---------------- graph structure build ----------------
__global__ void k_zero() {
    int i = blockIdx.x * 256 + threadIdx.x;
    if (i < NNODE) g_deg[i] = 0;
}

__global__ void k_hist(const int* __restrict__ ei) {
    int e = blockIdx.x * 256 + threadIdx.x;
    if (e >= E2) return;
    int d = (e < NEDGE) ? ei[NEDGE + e] : ei[e - NEDGE];
    atomicAdd(&g_deg[d], 1);
}

// warp-shuffle block scan (single block, 1024 threads, 20 elems/thread)
__global__ void k_scan() {
    __shared__ int wsum[32];
    int t = threadIdx.x, lane = t & 31, wid = t >> 5;
    const int PER = 20;                       // 1024*20 = 20480 >= NNODE
    int base = t * PER;
    int s = 0;
#pragma unroll
    for (int i = 0; i < PER; i++) { int idx = base + i; if (idx < NNODE) s += g_deg[idx]; }
    int x = s;
#pragma unroll
    for (int off = 1; off < 32; off <<= 1) {
        int y = __shfl_up_sync(0xffffffffu, x, off);
        if (lane >= off) x += y;
    }
    if (lane == 31) wsum[wid] = x;
    __syncthreads();
    if (wid == 0) {
        int y = wsum[lane];
#pragma unroll
        for (int off = 1; off < 32; off <<= 1) {
            int z = __shfl_up_sync(0xffffffffu, y, off);
            if (lane >= off) y += z;
        }
        wsum[lane] = y;
    }
    __syncthreads();
    int run = x - s + (wid > 0 ? wsum[wid - 1] : 0);
#pragma unroll
    for (int i = 0; i < PER; i++) {
        int idx = base + i;
        if (idx < NNODE) {
            int v = g_deg[idx];
            g_rowoff[idx] = run;
            g_cursor[idx] = run;
            g_dis[idx] = (v > 0) ? rsqrtf((float)v) : 0.f;
            run += v;
        }
    }
}

__global__ void k_scatter(const int* __restrict__ ei) {
    int e = blockIdx.x * 256 + threadIdx.x;
    if (e >= E2) return;
    int srcv = ei[e];  // both halves: [0,E)=src row, [E,2E)=dst row reversed
    int d  = (e < NEDGE) ? ei[NEDGE + e] : ei[e - NEDGE];
    int ea = (e < NEDGE) ? e : e - NEDGE;
    int slot = atomicAdd(&g_cursor[d], 1);
    g_csr_src[slot] = srcv;
    g_csr_ea[slot]  = ea;
}

// ---------------- mask MLP + residual: g_h0 = mlp2(mask) + x ----------------
__global__ void __launch_bounds__(128) k_maskmlp(
    const float* __restrict__ x, const float* __restrict__ mask,
    const float* __restrict__ w1, const float* __restrict__ b1,
    const float* __restrict__ w2, const float* __restrict__ b2)
{
    constexpr int T = 16;
    __shared__ __align__(16) float sM[T * NF];
    __shared__ __align__(16) float sH[T * HH];
    int tid = threadIdx.x;
    int n0 = blockIdx.x * T;
    for (int o = tid; o < T * NF; o += 128) sM[o] = mask[n0 * NF + o];
    __syncthreads();

    float acc[T];
    float bj = b1[tid];
#pragma unroll
    for (int t = 0; t < T; t++) acc[t] = bj;
#pragma unroll
    for (int i = 0; i < NF; i += 4) {
        float wa = w1[(i + 0) * HH + tid], wb = w1[(i + 1) * HH + tid];
        float wc = w1[(i + 2) * HH + tid], wd = w1[(i + 3) * HH + tid];
#pragma unroll
        for (int t = 0; t < T; t++) {
            float4 v = *reinterpret_cast<const float4*>(&sM[t * NF + i]);
            acc[t] = fmaf(v.x, wa, acc[t]); acc[t] = fmaf(v.y, wb, acc[t]);
            acc[t] = fmaf(v.z, wc, acc[t]); acc[t] = fmaf(v.w, wd, acc[t]);
        }
    }
#pragma unroll
    for (int t = 0; t < T; t++) sH[t * HH + tid] = fmaxf(acc[t], 0.f);
    __syncthreads();

    for (int o = tid; o < T * NF; o += 128) {
        int t = o >> 4, c = o & 15;
        float v = b2[c];
#pragma unroll 1
        for (int k = 0; k < HH; k += 4) {
            float4 h = *reinterpret_cast<const float4*>(&sH[t * HH + k]);
            v = fmaf(h.x, w2[(k + 0) * NF + c], v);
            v = fmaf(h.y, w2[(k + 1) * NF + c], v);
            v = fmaf(h.z, w2[(k + 2) * NF + c], v);
            v = fmaf(h.w, w2[(k + 3) * NF + c], v);
        }
        g_h0[n0 * NF + o] = v + x[n0 * NF + o];
    }
}

// ---------------- GEMM: out[M,128] = op(in[M,K] @ W[K,128])  (scalar FFMA) ----
// BIASMODE: 0 = none, 1 = +bias, 2 = +deg[n]*bias.
template <int K, int BIASMODE, bool RELU>
__global__ void __launch_bounds__(128) k_mm(
    int insel, const float* __restrict__ in_ext,
    float* __restrict__ outp,
    const float* __restrict__ W, const float* __restrict__ bias)
{
    constexpr int T = 16;
    __shared__ __align__(16) float sIn[T * K];
    const float* in = sel_in(insel, in_ext);
    int tid = threadIdx.x;
    int j = tid;
    int n0 = blockIdx.x * T;

    const float4* gsrc = reinterpret_cast<const float4*>(in + (size_t)n0 * K);
    float4* ssrc = reinterpret_cast<float4*>(sIn);
    for (int o = tid; o < T * K / 4; o += 128) ssrc[o] = gsrc[o];
    __syncthreads();

    float acc[T];
    if (BIASMODE == 1) {
        float b = bias[j];
#pragma unroll
        for (int t = 0; t < T; t++) acc[t] = b;
    } else {
#pragma unroll
        for (int t = 0; t < T; t++) acc[t] = 0.f;
    }

#pragma unroll 1
    for (int k = 0; k < K; k += 4) {
        float wa = W[(k + 0) * HH + j], wb = W[(k + 1) * HH + j];
        float wc = W[(k + 2) * HH + j], wd = W[(k + 3) * HH + j];
#pragma unroll
        for (int t = 0; t < T; t++) {
            float4 v = *reinterpret_cast<const float4*>(&sIn[t * K + k]);
            acc[t] = fmaf(v.x, wa, acc[t]); acc[t] = fmaf(v.y, wb, acc[t]);
            acc[t] = fmaf(v.z, wc, acc[t]); acc[t] = fmaf(v.w, wd, acc[t]);
        }
    }

    float bscale = (BIASMODE == 2) ? bias[j] : 0.f;
#pragma unroll
    for (int t = 0; t < T; t++) {
        float v = acc[t];
        if (BIASMODE == 2) v += bscale * (float)g_deg[n0 + t];
        if (RELU) v = fmaxf(v, 0.f);
        outp[(size_t)(n0 + t) * HH + j] = v;
    }
}

// ---------------- twin GEMM: nb0 = in@WA + biasA ; nb1 = in@WB  (shared input) ----
template <int K>
__global__ void __launch_bounds__(256) k_mmAB(
    int insel, const float* __restrict__ in_ext,
    const float* __restrict__ WA, const float* __restrict__ biasA,
    const float* __restrict__ WB)
{
    constexpr int T = 16;
    __shared__ __align__(16) float sIn[T * K];
    const float* in = sel_in(insel, in_ext);
    int tid = threadIdx.x;
    int j = tid & 127;
    bool isA = tid < 128;
    const float* W = isA ? WA : WB;
    float* out = isA ? g_nb[0] : g_nb[1];
    int n0 = blockIdx.x * T;

    const float4* gsrc = reinterpret_cast<const float4*>(in + (size_t)n0 * K);
    float4* ssrc = reinterpret_cast<float4*>(sIn);
    for (int o = tid; o < T * K / 4; o += 256) ssrc[o] = gsrc[o];
    __syncthreads();

    float acc[T];
    float b = isA ? biasA[j] : 0.f;
#pragma unroll
    for (int t = 0; t < T; t++) acc[t] = b;

#pragma unroll 1
    for (int k = 0; k < K; k += 4) {
        float wa = W[(k + 0) * HH + j], wb = W[(k + 1) * HH + j];
        float wc = W[(k + 2) * HH + j], wd = W[(k + 3) * HH + j];
#pragma unroll
        for (int t = 0; t < T; t++) {
            float4 v = *reinterpret_cast<const float4*>(&sIn[t * K + k]);
            acc[t] = fmaf(v.x, wa, acc[t]); acc[t] = fmaf(v.y, wb, acc[t]);
            acc[t] = fmaf(v.z, wc, acc[t]); acc[t] = fmaf(v.w, wd, acc[t]);
        }
    }
#pragma unroll
    for (int t = 0; t < T; t++)
        out[(size_t)(n0 + t) * HH + j] = acc[t];
}

// ---------------- triple edge-C GEMM: msg[r] = eattr @ Wc_r  (r = 0..2) ----------
__global__ void __launch_bounds__(128) k_mmC(
    const float* __restrict__ eattr,
    const float* __restrict__ W0, const float* __restrict__ W1,
    const float* __restrict__ W2)
{
    constexpr int T = 16, K = 16;
    __shared__ __align__(16) float sIn[T * K];
    int tid = threadIdx.x;
    int j = tid;
    int e0 = blockIdx.x * T;

    const float4* gsrc = reinterpret_cast<const float4*>(eattr + (size_t)e0 * K);
    float4* ssrc = reinterpret_cast<float4*>(sIn);
    for (int o = tid; o < T * K / 4; o += 128) ssrc[o] = gsrc[o];
    __syncthreads();

    const float* Ws[3] = {W0, W1, W2};
#pragma unroll 1
    for (int r = 0; r < 3; r++) {
        const float* W = Ws[r];
        float acc[T];
#pragma unroll
        for (int t = 0; t < T; t++) acc[t] = 0.f;
#pragma unroll
        for (int k = 0; k < K; k += 4) {
            float wa = W[(k + 0) * HH + j], wb = W[(k + 1) * HH + j];
            float wc = W[(k + 2) * HH + j], wd = W[(k + 3) * HH + j];
#pragma unroll
            for (int t = 0; t < T; t++) {
                float4 v = *reinterpret_cast<const float4*>(&sIn[t * K + k]);
                acc[t] = fmaf(v.x, wa, acc[t]); acc[t] = fmaf(v.y, wb, acc[t]);
                acc[t] = fmaf(v.z, wc, acc[t]); acc[t] = fmaf(v.w, wd, acc[t]);
            }
        }
#pragma unroll
        for (int t = 0; t < T; t++)
            g_msg[r][(size_t)(e0 + t) * HH + j] = acc[t];
    }
}

// ---------------- fused TAG GEMM: nb4 = relu([h0|h1|h2|h3] @ tagw[0..3] + b) ----
// Reads nb3 (h0), nb0 (h1), nb1 (h2), nb2 (h3); tagw is [4,128,128] contiguous.
__global__ void __launch_bounds__(128) k_mmTAG(
    const float* __restrict__ tagw, const float* __restrict__ tagb)
{
    constexpr int T = 16, K = 512;
    __shared__ __align__(16) float sIn[T * K];   // 32 KB
    int tid = threadIdx.x;
    int j = tid;
    int n0 = blockIdx.x * T;

    const float* bufs0 = g_nb[3];
    const float* bufs1 = g_nb[0];
    const float* bufs2 = g_nb[1];
    const float* bufs3 = g_nb[2];
    for (int o = tid; o < T * K / 4; o += 128) {
        int f = o * 4;
        int t = f >> 9;
        int seg = (f >> 7) & 3;
        int c = f & 127;
        const float* b = (seg == 0) ? bufs0 : (seg == 1) ? bufs1 : (seg == 2) ? bufs2 : bufs3;
        reinterpret_cast<float4*>(sIn)[o] =
            *reinterpret_cast<const float4*>(&b[(size_t)(n0 + t) * HH + c]);
    }
    __syncthreads();

    float acc[T];
    float bj = tagb[j];
#pragma unroll
    for (int t = 0; t < T; t++) acc[t] = bj;

#pragma unroll 1
    for (int k = 0; k < K; k += 4) {
        float wa = tagw[(k + 0) * HH + j], wb = tagw[(k + 1) * HH + j];
        float wc = tagw[(k + 2) * HH + j], wd = tagw[(k + 3) * HH + j];
#pragma unroll
        for (int t = 0; t < T; t++) {
            float4 v = *reinterpret_cast<const float4*>(&sIn[t * K + k]);
            acc[t] = fmaf(v.x, wa, acc[t]); acc[t] = fmaf(v.y, wb, acc[t]);
            acc[t] = fmaf(v.z, wc, acc[t]); acc[t] = fmaf(v.w, wd, acc[t]);
        }
    }
#pragma unroll
    for (int t = 0; t < T; t++)
        g_nb[4][(size_t)(n0 + t) * HH + j] = fmaxf(acc[t], 0.f);
}

// ---------------- fused hidden + aggregation ----------------
// S[n] = sum over incident edges of relu(A[n] + B[src] + C[ea])
__global__ void k_fused_agg(int msel) {
    const float* __restrict__ A = g_nb[0];
    const float* __restrict__ B = g_nb[1];
    const float* __restrict__ M = g_msg[msel];
    float* __restrict__ S = g_nb[2];
    int n = blockIdx.x, j = threadIdx.x;
    int beg = g_rowoff[n], len = g_deg[n];
    float a = A[(size_t)n * HH + j];
    float acc = 0.f;
    int i = 0;
    for (; i + 4 <= len; i += 4) {
        int s0 = __ldg(&g_csr_src[beg + i + 0]), e0 = __ldg(&g_csr_ea[beg + i + 0]);
        int s1 = __ldg(&g_csr_src[beg + i + 1]), e1 = __ldg(&g_csr_ea[beg + i + 1]);
        int s2 = __ldg(&g_csr_src[beg + i + 2]), e2 = __ldg(&g_csr_ea[beg + i + 2]);
        int s3 = __ldg(&g_csr_src[beg + i + 3]), e3 = __ldg(&g_csr_ea[beg + i + 3]);
        float b0 = __ldg(&B[(size_t)s0 * HH + j]), c0 = __ldg(&M[(size_t)e0 * HH + j]);
        float b1 = __ldg(&B[(size_t)s1 * HH + j]), c1 = __ldg(&M[(size_t)e1 * HH + j]);
        float b2 = __ldg(&B[(size_t)s2 * HH + j]), c2 = __ldg(&M[(size_t)e2 * HH + j]);
        float b3 = __ldg(&B[(size_t)s3 * HH + j]), c3 = __ldg(&M[(size_t)e3 * HH + j]);
        acc += fmaxf(a + b0 + c0, 0.f);
        acc += fmaxf(a + b1 + c1, 0.f);
        acc += fmaxf(a + b2 + c2, 0.f);
        acc += fmaxf(a + b3 + c3, 0.f);
    }
    for (; i < len; i++) {
        int s  = __ldg(&g_csr_src[beg + i]);
        int ea = __ldg(&g_csr_ea[beg + i]);
        acc += fmaxf(a + __ldg(&B[(size_t)s * HH + j]) + __ldg(&M[(size_t)ea * HH + j]), 0.f);
    }
    S[(size_t)n * HH + j] = acc;
}

// ---------------- TAG propagation hop: out[n] = dis[n] * sum dis[s] * h[s] ----------------
__global__ void k_hop(int insel, int outsel) {
    const float* __restrict__ hin = g_nb[insel];
    float* __restrict__ hout = g_nb[outsel];
    int n = blockIdx.x, j = threadIdx.x;
    int beg = g_rowoff[n], len = g_deg[n];
    float acc = 0.f;
    int i = 0;
    for (; i + 4 <= len; i += 4) {
        int s0 = __ldg(&g_csr_src[beg + i + 0]);
        int s1 = __ldg(&g_csr_src[beg + i + 1]);
        int s2 = __ldg(&g_csr_src[beg + i + 2]);
        int s3 = __ldg(&g_csr_src[beg + i + 3]);
        float d0 = __ldg(&g_dis[s0]), h0 = __ldg(&hin[(size_t)s0 * HH + j]);
        float d1 = __ldg(&g_dis[s1]), h1 = __ldg(&hin[(size_t)s1 * HH + j]);
        float d2 = __ldg(&g_dis[s2]), h2 = __ldg(&hin[(size_t)s2 * HH + j]);
        float d3 = __ldg(&g_dis[s3]), h3 = __ldg(&hin[(size_t)s3 * HH + j]);
        acc = fmaf(d0, h0, acc); acc = fmaf(d1, h1, acc);
        acc = fmaf(d2, h2, acc); acc = fmaf(d3, h3, acc);
    }
    for (; i < len; i++) {
        int s = __ldg(&g_csr_src[beg + i]);
        acc = fmaf(__ldg(&g_dis[s]), __ldg(&hin[(size_t)s * HH + j]), acc);
    }
    hout[(size_t)n * HH + j] = g_dis[n] * acc;
}

// ---------------- final: out[n,16] = S[n]@W2[128,16] + deg[n]*b2 ----------------
__global__ void __launch_bounds__(128) k_out16(
    float* __restrict__ out, const float* __restrict__ W2, const float* __restrict__ b2)
{
    int tid = threadIdx.x;
    int n = blockIdx.x * 8 + (tid >> 4);
    int c = tid & 15;
    const float* S = g_nb[2];
    float acc = b2[c] * (float)g_deg[n];
#pragma unroll 4
    for (int k = 0; k < HH; k++)
        acc = fmaf(__ldg(&S[(size_t)n * HH + k]), __ldg(&W2[k * 16 + c]), acc);
    out[n * 16 + c] = acc;
}

// ---------------- launch ----------------
extern "C" void kernel_launch(void* const* d_in, const int* in_sizes, int n_in,
                              void* d_out, int out_size)
{
    static const int ESZ[24] = {
        320000, 320000, 2560000, 320000,
        2048, 128, 2048, 16,
        6144, 128, 16384, 128,
        65536, 128,
        34816, 128, 16384, 128,
        65536, 128,
        34816, 128, 2048, 16};
    static const int M_DICT[24] = {0,1,2,3,4,5,6,7,8,9,10,11,12,13,14,15,16,17,18,19,20,21,22,23};
    static const int M_SIG[24]  = {0,1,2,23,3,4,5,6,7,8,9,10,11,12,13,14,15,16,17,18,19,20,21,22};
    static const int M_ALPHA[24]= {23,18,12,13,16,14,17,15,2,0,3,1,20,19,6,4,7,5,22,21,10,8,11,9};
    const int* cands[3] = {M_DICT, M_SIG, M_ALPHA};
    const int* map = M_DICT;
    for (int ci = 0; ci < 3; ci++) {
        bool ok = (n_in >= 24);
        for (int l = 0; l < 24 && ok; l++) ok = (in_sizes[cands[ci][l]] == ESZ[l]);
        if (ok) { map = cands[ci]; break; }
    }
#define INP(l) ((const float*)d_in[map[l]])
    const float* x     = INP(0);
    const float* mask  = INP(1);
    const float* eattr = INP(2);
    const int*   ei    = (const int*)d_in[map[3]];
    const float *m_w1 = INP(4), *m_b1 = INP(5), *m_w2 = INP(6), *m_b2 = INP(7);
    const float *ea0w1 = INP(8), *ea0b1 = INP(9), *ea0w2 = INP(10), *ea0b2 = INP(11);
    const float *tag0w = INP(12), *tag0b = INP(13);
    const float *ea1w1 = INP(14), *ea1b1 = INP(15), *ea1w2 = INP(16), *ea1b2 = INP(17);
    const float *tag1w = INP(18), *tag1b = INP(19);
    const float *ea2w1 = INP(20), *ea2b1 = INP(21), *ea2w2 = INP(22), *ea2b2 = INP(23);
#undef INP
    float* out = (float*)d_out;
    (void)out_size;

    const int GN = NNODE / 16;   // 1250 node-GEMM blocks
    const int GE = NEDGE / 16;   // 10000 edge-C blocks

    // resolve device-global addresses once (pure address query; no allocation)
    static float* s_nb3 = nullptr;
    if (!s_nb3) {
        void* p = nullptr;
        cudaGetSymbolAddress(&p, g_nb);
        s_nb3 = (float*)p + (size_t)3 * NNODE * HH;
    }

    // graph structure
    k_zero<<<(NNODE + 255) / 256, 256>>>();
    k_hist<<<E2 / 256, 256>>>(ei);
    k_scan<<<1, 1024>>>();
    k_scatter<<<E2 / 256, 256>>>(ei);

    // all three edge-attr C projections up front (shared input staging)
    k_mmC<<<GE, 128>>>(eattr, ea0w1 + 32 * HH, ea1w1 + 256 * HH, ea2w1 + 256 * HH);

    // node embedding
    k_maskmlp<<<GN, 128>>>(x, mask, m_w1, m_b1, m_w2, m_b2);

    // ---- EA0 (h0[16] -> 128): A,B twin GEMM; agg; layer-2 -> nb3 ----
    k_mmAB<16><<<GN, 256>>>(-3, nullptr, ea0w1, ea0b1, ea0w1 + 16 * HH);
    k_fused_agg<<<NNODE, 128>>>(0);
    k_mm<128, 2, true><<<GN, 128>>>(2, nullptr, s_nb3, ea0w2, ea0b2);

    // ---- TAG0: h0=nb3 -> hops nb0,nb1,nb2 -> fused K=512 GEMM -> nb4 ----
    k_hop<<<NNODE, 128>>>(3, 0);
    k_hop<<<NNODE, 128>>>(0, 1);
    k_hop<<<NNODE, 128>>>(1, 2);
    k_mmTAG<<<GN, 128>>>(tag0w, tag0b);

    // ---- EA1 (nb4 -> 128) -> nb3 ----
    k_mmAB<128><<<GN, 256>>>(4, nullptr, ea1w1, ea1b1, ea1w1 + 128 * HH);
    k_fused_agg<<<NNODE, 128>>>(1);
    k_mm<128, 2, true><<<GN, 128>>>(2, nullptr, s_nb3, ea1w2, ea1b2);

    // ---- TAG1 ----
    k_hop<<<NNODE, 128>>>(3, 0);
    k_hop<<<NNODE, 128>>>(0, 1);
    k_hop<<<NNODE, 128>>>(1, 2);
    k_mmTAG<<<GN, 128>>>(tag1w, tag1b);

    // ---- EA2 (nb4 -> 16) -> d_out ----
    k_mmAB<128><<<GN, 256>>>(4, nullptr, ea2w1, ea2b1, ea2w1 + 128 * HH);
    k_fused_agg<<<NNODE, 128>>>(2);
    k_out16<<<NNODE / 8, 128>>>(out, ea2w2, ea2b2);
}

// round 7
// speedup vs baseline: 1.0510x; 1.0179x over previous
#include <cuda_runtime.h>
#include <math.h>

#define NNODE 20000
#define NEDGE 160000
#define E2    320000
#define HH    128
#define NF    16
#define EF    16

// ---------------- device scratch (no allocations allowed) ----------------
__device__ int   g_deg[NNODE];
__device__ int   g_rowoff[NNODE];
__device__ int   g_cursor[NNODE];
__device__ float g_dis[NNODE];
__device__ int   g_csr_src[E2];
__device__ int   g_csr_ea[E2];                 // eattr index (0..NEDGE)
__device__ float g_h0[NNODE * NF];
__device__ float g_nb[5][NNODE * HH];          // node-feature buffers
__device__ float g_msg[3][(size_t)NEDGE * HH]; // per-unique-edge C buffers (3 x 82 MB)

__device__ __forceinline__ const float* sel_in(int s, const float* ext) {
    if (s >= 0) return g_nb[s];
    if (s == -3) return g_h0;
    return ext;
}

// ---------------- graph structure build ----------------
__global__ void k_zero() {
    int i = blockIdx.x * 256 + threadIdx.x;
    if (i < NNODE) g_deg[i] = 0;
}

__global__ void k_hist(const int* __restrict__ ei) {
    int e = blockIdx.x * 256 + threadIdx.x;
    if (e >= E2) return;
    int d = (e < NEDGE) ? ei[NEDGE + e] : ei[e - NEDGE];
    atomicAdd(&g_deg[d], 1);
}

// warp-shuffle block scan (single block, 1024 threads, 20 elems/thread)
__global__ void k_scan() {
    __shared__ int wsum[32];
    int t = threadIdx.x, lane = t & 31, wid = t >> 5;
    const int PER = 20;                       // 1024*20 = 20480 >= NNODE
    int base = t * PER;
    int s = 0;
#pragma unroll
    for (int i = 0; i < PER; i++) { int idx = base + i; if (idx < NNODE) s += g_deg[idx]; }
    int x = s;
#pragma unroll
    for (int off = 1; off < 32; off <<= 1) {
        int y = __shfl_up_sync(0xffffffffu, x, off);
        if (lane >= off) x += y;
    }
    if (lane == 31) wsum[wid] = x;
    __syncthreads();
    if (wid == 0) {
        int y = wsum[lane];
#pragma unroll
        for (int off = 1; off < 32; off <<= 1) {
            int z = __shfl_up_sync(0xffffffffu, y, off);
            if (lane >= off) y += z;
        }
        wsum[lane] = y;
    }
    __syncthreads();
    int run = x - s + (wid > 0 ? wsum[wid - 1] : 0);
#pragma unroll
    for (int i = 0; i < PER; i++) {
        int idx = base + i;
        if (idx < NNODE) {
            int v = g_deg[idx];
            g_rowoff[idx] = run;
            g_cursor[idx] = run;
            g_dis[idx] = (v > 0) ? rsqrtf((float)v) : 0.f;
            run += v;
        }
    }
}

__global__ void k_scatter(const int* __restrict__ ei) {
    int e = blockIdx.x * 256 + threadIdx.x;
    if (e >= E2) return;
    int srcv = ei[e];  // both halves: [0,E)=src row, [E,2E)=dst row reversed
    int d  = (e < NEDGE) ? ei[NEDGE + e] : ei[e - NEDGE];
    int ea = (e < NEDGE) ? e : e - NEDGE;
    int slot = atomicAdd(&g_cursor[d], 1);
    g_csr_src[slot] = srcv;
    g_csr_ea[slot]  = ea;
}

// ---------------- mask MLP + residual: g_h0 = mlp2(mask) + x ----------------
__global__ void __launch_bounds__(128) k_maskmlp(
    const float* __restrict__ x, const float* __restrict__ mask,
    const float* __restrict__ w1, const float* __restrict__ b1,
    const float* __restrict__ w2, const float* __restrict__ b2)
{
    constexpr int T = 16;
    __shared__ __align__(16) float sM[T * NF];
    __shared__ __align__(16) float sH[T * HH];
    int tid = threadIdx.x;
    int n0 = blockIdx.x * T;
    for (int o = tid; o < T * NF; o += 128) sM[o] = mask[n0 * NF + o];
    __syncthreads();

    float acc[T];
    float bj = b1[tid];
#pragma unroll
    for (int t = 0; t < T; t++) acc[t] = bj;
#pragma unroll
    for (int i = 0; i < NF; i += 4) {
        float wa = w1[(i + 0) * HH + tid], wb = w1[(i + 1) * HH + tid];
        float wc = w1[(i + 2) * HH + tid], wd = w1[(i + 3) * HH + tid];
#pragma unroll
        for (int t = 0; t < T; t++) {
            float4 v = *reinterpret_cast<const float4*>(&sM[t * NF + i]);
            acc[t] = fmaf(v.x, wa, acc[t]); acc[t] = fmaf(v.y, wb, acc[t]);
            acc[t] = fmaf(v.z, wc, acc[t]); acc[t] = fmaf(v.w, wd, acc[t]);
        }
    }
#pragma unroll
    for (int t = 0; t < T; t++) sH[t * HH + tid] = fmaxf(acc[t], 0.f);
    __syncthreads();

    for (int o = tid; o < T * NF; o += 128) {
        int t = o >> 4, c = o & 15;
        float v = b2[c];
#pragma unroll 1
        for (int k = 0; k < HH; k += 4) {
            float4 h = *reinterpret_cast<const float4*>(&sH[t * HH + k]);
            v = fmaf(h.x, w2[(k + 0) * NF + c], v);
            v = fmaf(h.y, w2[(k + 1) * NF + c], v);
            v = fmaf(h.z, w2[(k + 2) * NF + c], v);
            v = fmaf(h.w, w2[(k + 3) * NF + c], v);
        }
        g_h0[n0 * NF + o] = v + x[n0 * NF + o];
    }
}

// ---------------- GEMM: out[M,128] = op(in[M,K] @ W[K,128])  (scalar FFMA) ----
// BIASMODE: 0 = none, 1 = +bias, 2 = +deg[n]*bias.
template <int K, int BIASMODE, bool RELU>
__global__ void __launch_bounds__(128) k_mm(
    int insel, const float* __restrict__ in_ext,
    float* __restrict__ outp,
    const float* __restrict__ W, const float* __restrict__ bias)
{
    constexpr int T = 16;
    __shared__ __align__(16) float sIn[T * K];
    const float* in = sel_in(insel, in_ext);
    int tid = threadIdx.x;
    int j = tid;
    int n0 = blockIdx.x * T;

    const float4* gsrc = reinterpret_cast<const float4*>(in + (size_t)n0 * K);
    float4* ssrc = reinterpret_cast<float4*>(sIn);
    for (int o = tid; o < T * K / 4; o += 128) ssrc[o] = gsrc[o];
    __syncthreads();

    float acc[T];
    if (BIASMODE == 1) {
        float b = bias[j];
#pragma unroll
        for (int t = 0; t < T; t++) acc[t] = b;
    } else {
#pragma unroll
        for (int t = 0; t < T; t++) acc[t] = 0.f;
    }

#pragma unroll 1
    for (int k = 0; k < K; k += 4) {
        float wa = W[(k + 0) * HH + j], wb = W[(k + 1) * HH + j];
        float wc = W[(k + 2) * HH + j], wd = W[(k + 3) * HH + j];
#pragma unroll
        for (int t = 0; t < T; t++) {
            float4 v = *reinterpret_cast<const float4*>(&sIn[t * K + k]);
            acc[t] = fmaf(v.x, wa, acc[t]); acc[t] = fmaf(v.y, wb, acc[t]);
            acc[t] = fmaf(v.z, wc, acc[t]); acc[t] = fmaf(v.w, wd, acc[t]);
        }
    }

    float bscale = (BIASMODE == 2) ? bias[j] : 0.f;
#pragma unroll
    for (int t = 0; t < T; t++) {
        float v = acc[t];
        if (BIASMODE == 2) v += bscale * (float)g_deg[n0 + t];
        if (RELU) v = fmaxf(v, 0.f);
        outp[(size_t)(n0 + t) * HH + j] = v;
    }
}

// ---------------- triple edge-C GEMM: msg[r] = eattr @ Wc_r  (r = 0..2) ----------
__global__ void __launch_bounds__(128) k_mmC(
    const float* __restrict__ eattr,
    const float* __restrict__ W0, const float* __restrict__ W1,
    const float* __restrict__ W2)
{
    constexpr int T = 16, K = 16;
    __shared__ __align__(16) float sIn[T * K];
    int tid = threadIdx.x;
    int j = tid;
    int e0 = blockIdx.x * T;

    const float4* gsrc = reinterpret_cast<const float4*>(eattr + (size_t)e0 * K);
    float4* ssrc = reinterpret_cast<float4*>(sIn);
    for (int o = tid; o < T * K / 4; o += 128) ssrc[o] = gsrc[o];
    __syncthreads();

    const float* Ws[3] = {W0, W1, W2};
#pragma unroll 1
    for (int r = 0; r < 3; r++) {
        const float* W = Ws[r];
        float acc[T];
#pragma unroll
        for (int t = 0; t < T; t++) acc[t] = 0.f;
#pragma unroll
        for (int k = 0; k < K; k += 4) {
            float wa = W[(k + 0) * HH + j], wb = W[(k + 1) * HH + j];
            float wc = W[(k + 2) * HH + j], wd = W[(k + 3) * HH + j];
#pragma unroll
            for (int t = 0; t < T; t++) {
                float4 v = *reinterpret_cast<const float4*>(&sIn[t * K + k]);
                acc[t] = fmaf(v.x, wa, acc[t]); acc[t] = fmaf(v.y, wb, acc[t]);
                acc[t] = fmaf(v.z, wc, acc[t]); acc[t] = fmaf(v.w, wd, acc[t]);
            }
        }
#pragma unroll
        for (int t = 0; t < T; t++)
            g_msg[r][(size_t)(e0 + t) * HH + j] = acc[t];
    }
}

// ---------------- fused TAG GEMM: nb4 = relu([h0|h1|h2|h3] @ tagw[0..3] + b) ----
// Reads nb3 (h0), nb0 (h1), nb1 (h2), nb2 (h3); tagw is [4,128,128] contiguous.
__global__ void __launch_bounds__(128) k_mmTAG(
    const float* __restrict__ tagw, const float* __restrict__ tagb)
{
    constexpr int T = 16, K = 512;
    __shared__ __align__(16) float sIn[T * K];   // 32 KB
    int tid = threadIdx.x;
    int j = tid;
    int n0 = blockIdx.x * T;

    const float* bufs0 = g_nb[3];
    const float* bufs1 = g_nb[0];
    const float* bufs2 = g_nb[1];
    const float* bufs3 = g_nb[2];
    for (int o = tid; o < T * K / 4; o += 128) {
        int f = o * 4;
        int t = f >> 9;
        int seg = (f >> 7) & 3;
        int c = f & 127;
        const float* b = (seg == 0) ? bufs0 : (seg == 1) ? bufs1 : (seg == 2) ? bufs2 : bufs3;
        reinterpret_cast<float4*>(sIn)[o] =
            *reinterpret_cast<const float4*>(&b[(size_t)(n0 + t) * HH + c]);
    }
    __syncthreads();

    float acc[T];
    float bj = tagb[j];
#pragma unroll
    for (int t = 0; t < T; t++) acc[t] = bj;

#pragma unroll 1
    for (int k = 0; k < K; k += 4) {
        float wa = tagw[(k + 0) * HH + j], wb = tagw[(k + 1) * HH + j];
        float wc = tagw[(k + 2) * HH + j], wd = tagw[(k + 3) * HH + j];
#pragma unroll
        for (int t = 0; t < T; t++) {
            float4 v = *reinterpret_cast<const float4*>(&sIn[t * K + k]);
            acc[t] = fmaf(v.x, wa, acc[t]); acc[t] = fmaf(v.y, wb, acc[t]);
            acc[t] = fmaf(v.z, wc, acc[t]); acc[t] = fmaf(v.w, wd, acc[t]);
        }
    }
#pragma unroll
    for (int t = 0; t < T; t++)
        g_nb[4][(size_t)(n0 + t) * HH + j] = fmaxf(acc[t], 0.f);
}

// ---------------- fused hidden + aggregation ----------------
// S[n] = sum over incident edges of relu(A[n] + B[src] + C[ea])
__global__ void k_fused_agg(int msel) {
    const float* __restrict__ A = g_nb[0];
    const float* __restrict__ B = g_nb[1];
    const float* __restrict__ M = g_msg[msel];
    float* __restrict__ S = g_nb[2];
    int n = blockIdx.x, j = threadIdx.x;
    int beg = g_rowoff[n], len = g_deg[n];
    float a = A[(size_t)n * HH + j];
    float acc = 0.f;
    for (int i = 0; i < len; i++) {
        int s  = __ldg(&g_csr_src[beg + i]);
        int ea = __ldg(&g_csr_ea[beg + i]);
        acc += fmaxf(a + __ldg(&B[(size_t)s * HH + j]) + __ldg(&M[(size_t)ea * HH + j]), 0.f);
    }
    S[(size_t)n * HH + j] = acc;
}

// ---------------- TAG propagation hop: out[n] = dis[n] * sum dis[s] * h[s] ----------------
__global__ void k_hop(int insel, int outsel) {
    const float* __restrict__ hin = g_nb[insel];
    float* __restrict__ hout = g_nb[outsel];
    int n = blockIdx.x, j = threadIdx.x;
    int beg = g_rowoff[n], len = g_deg[n];
    float acc = 0.f;
    for (int i = 0; i < len; i++) {
        int s = __ldg(&g_csr_src[beg + i]);
        acc = fmaf(__ldg(&g_dis[s]), __ldg(&hin[(size_t)s * HH + j]), acc);
    }
    hout[(size_t)n * HH + j] = g_dis[n] * acc;
}

// ---------------- final: out[n,16] = S[n]@W2[128,16] + deg[n]*b2 ----------------
__global__ void __launch_bounds__(128) k_out16(
    float* __restrict__ out, const float* __restrict__ W2, const float* __restrict__ b2)
{
    int tid = threadIdx.x;
    int n = blockIdx.x * 8 + (tid >> 4);
    int c = tid & 15;
    const float* S = g_nb[2];
    float acc = b2[c] * (float)g_deg[n];
#pragma unroll 4
    for (int k = 0; k < HH; k++)
        acc = fmaf(__ldg(&S[(size_t)n * HH + k]), __ldg(&W2[k * 16 + c]), acc);
    out[n * 16 + c] = acc;
}

// ---------------- launch ----------------
extern "C" void kernel_launch(void* const* d_in, const int* in_sizes, int n_in,
                              void* d_out, int out_size)
{
    static const int ESZ[24] = {
        320000, 320000, 2560000, 320000,
        2048, 128, 2048, 16,
        6144, 128, 16384, 128,
        65536, 128,
        34816, 128, 16384, 128,
        65536, 128,
        34816, 128, 2048, 16};
    static const int M_DICT[24] = {0,1,2,3,4,5,6,7,8,9,10,11,12,13,14,15,16,17,18,19,20,21,22,23};
    static const int M_SIG[24]  = {0,1,2,23,3,4,5,6,7,8,9,10,11,12,13,14,15,16,17,18,19,20,21,22};
    static const int M_ALPHA[24]= {23,18,12,13,16,14,17,15,2,0,3,1,20,19,6,4,7,5,22,21,10,8,11,9};
    const int* cands[3] = {M_DICT, M_SIG, M_ALPHA};
    const int* map = M_DICT;
    for (int ci = 0; ci < 3; ci++) {
        bool ok = (n_in >= 24);
        for (int l = 0; l < 24 && ok; l++) ok = (in_sizes[cands[ci][l]] == ESZ[l]);
        if (ok) { map = cands[ci]; break; }
    }
#define INP(l) ((const float*)d_in[map[l]])
    const float* x     = INP(0);
    const float* mask  = INP(1);
    const float* eattr = INP(2);
    const int*   ei    = (const int*)d_in[map[3]];
    const float *m_w1 = INP(4), *m_b1 = INP(5), *m_w2 = INP(6), *m_b2 = INP(7);
    const float *ea0w1 = INP(8), *ea0b1 = INP(9), *ea0w2 = INP(10), *ea0b2 = INP(11);
    const float *tag0w = INP(12), *tag0b = INP(13);
    const float *ea1w1 = INP(14), *ea1b1 = INP(15), *ea1w2 = INP(16), *ea1b2 = INP(17);
    const float *tag1w = INP(18), *tag1b = INP(19);
    const float *ea2w1 = INP(20), *ea2b1 = INP(21), *ea2w2 = INP(22), *ea2b2 = INP(23);
#undef INP
    float* out = (float*)d_out;
    (void)out_size;

    const int GN = NNODE / 16;   // 1250 node-GEMM blocks
    const int GE = NEDGE / 16;   // 10000 edge-C blocks

    // one-time host-side resources: symbol addresses, side streams, fork/join events.
    // (address queries + stream/event creation only -- no device memory allocation;
    //  created on the first (non-capture) correctness call, reused during capture)
    static float* s_nb[5] = {nullptr, nullptr, nullptr, nullptr, nullptr};
    static cudaStream_t s1 = nullptr, s2 = nullptr;
    static cudaEvent_t evFork = nullptr, evS1 = nullptr, evS2 = nullptr;
    if (!s_nb[0]) {
        void* p = nullptr;
        cudaGetSymbolAddress(&p, g_nb);
        for (int i = 0; i < 5; i++) s_nb[i] = (float*)p + (size_t)i * NNODE * HH;
        cudaStreamCreateWithFlags(&s1, cudaStreamNonBlocking);
        cudaStreamCreateWithFlags(&s2, cudaStreamNonBlocking);
        cudaEventCreateWithFlags(&evFork, cudaEventDisableTiming);
        cudaEventCreateWithFlags(&evS1, cudaEventDisableTiming);
        cudaEventCreateWithFlags(&evS2, cudaEventDisableTiming);
    }

    // ---- fork: structure build on main; node/edge GEMMs on side streams ----
    cudaEventRecord(evFork, 0);
    cudaStreamWaitEvent(s1, evFork, 0);
    cudaStreamWaitEvent(s2, evFork, 0);

    // main stream: CSR build
    k_zero<<<(NNODE + 255) / 256, 256>>>();
    k_hist<<<E2 / 256, 256>>>(ei);
    k_scan<<<1, 1024>>>();
    k_scatter<<<E2 / 256, 256>>>(ei);

    // s1: node embedding + EA0 A/B projections (independent of CSR)
    k_maskmlp<<<GN, 128, 0, s1>>>(x, mask, m_w1, m_b1, m_w2, m_b2);
    k_mm<16, 1, false><<<GN, 128, 0, s1>>>(-3, nullptr, s_nb[0], ea0w1,           ea0b1);
    k_mm<16, 0, false><<<GN, 128, 0, s1>>>(-3, nullptr, s_nb[1], ea0w1 + 16 * HH, nullptr);

    // s2: all three edge-attr C projections (independent of CSR)
    k_mmC<<<GE, 128, 0, s2>>>(eattr, ea0w1 + 32 * HH, ea1w1 + 256 * HH, ea2w1 + 256 * HH);

    // join
    cudaEventRecord(evS1, s1);
    cudaEventRecord(evS2, s2);
    cudaStreamWaitEvent(0, evS1, 0);
    cudaStreamWaitEvent(0, evS2, 0);

    // ---- EA0: agg; layer-2 -> nb3 ----
    k_fused_agg<<<NNODE, 128>>>(0);
    k_mm<128, 2, true><<<GN, 128>>>(2, nullptr, s_nb[3], ea0w2, ea0b2);

    // ---- TAG0: h0=nb3 -> hops nb0,nb1,nb2 -> fused K=512 GEMM -> nb4 ----
    k_hop<<<NNODE, 128>>>(3, 0);
    k_hop<<<NNODE, 128>>>(0, 1);
    k_hop<<<NNODE, 128>>>(1, 2);
    k_mmTAG<<<GN, 128>>>(tag0w, tag0b);

    // ---- EA1 (nb4 -> 128) -> nb3 ----
    k_mm<128, 1, false><<<GN, 128>>>(4, nullptr, s_nb[0], ea1w1,            ea1b1);
    k_mm<128, 0, false><<<GN, 128>>>(4, nullptr, s_nb[1], ea1w1 + 128 * HH, nullptr);
    k_fused_agg<<<NNODE, 128>>>(1);
    k_mm<128, 2, true><<<GN, 128>>>(2, nullptr, s_nb[3], ea1w2, ea1b2);

    // ---- TAG1 ----
    k_hop<<<NNODE, 128>>>(3, 0);
    k_hop<<<NNODE, 128>>>(0, 1);
    k_hop<<<NNODE, 128>>>(1, 2);
    k_mmTAG<<<GN, 128>>>(tag1w, tag1b);

    // ---- EA2 (nb4 -> 16) -> d_out ----
    k_mm<128, 1, false><<<GN, 128>>>(4, nullptr, s_nb[0], ea2w1,            ea2b1);
    k_mm<128, 0, false><<<GN, 128>>>(4, nullptr, s_nb[1], ea2w1 + 128 * HH, nullptr);
    k_fused_agg<<<NNODE, 128>>>(2);
    k_out16<<<NNODE / 8, 128>>>(out, ea2w2, ea2b2);
}

// round 8
// speedup vs baseline: 1.0603x; 1.0089x over previous
#include <cuda_runtime.h>
#include <math.h>

#define NNODE 20000
#define NEDGE 160000
#define E2    320000
#define HH    128
#define NF    16
#define EF    16

// ---------------- device scratch (no allocations allowed) ----------------
__device__ int   g_deg[NNODE];
__device__ int   g_rowoff[NNODE];
__device__ int   g_cursor[NNODE];
__device__ float g_dis[NNODE];
__device__ int   g_csr_src[E2];
__device__ int   g_csr_ea[E2];                 // eattr index (0..NEDGE)
__device__ float g_h0[NNODE * NF];
__device__ float g_nb[5][NNODE * HH];          // node-feature buffers
__device__ float g_msg[3][(size_t)NEDGE * HH]; // per-unique-edge C buffers

__device__ __forceinline__ const float* sel_in(int s, const float* ext) {
    if (s >= 0) return g_nb[s];
    if (s == -3) return g_h0;
    return ext;
}

// ---------------- graph structure build ----------------
__global__ void k_zero() {
    int i = blockIdx.x * 256 + threadIdx.x;
    if (i < NNODE) g_deg[i] = 0;
}

__global__ void k_hist(const int* __restrict__ ei) {
    int e = blockIdx.x * 256 + threadIdx.x;
    if (e >= E2) return;
    int d = (e < NEDGE) ? ei[NEDGE + e] : ei[e - NEDGE];
    atomicAdd(&g_deg[d], 1);
}

// warp-shuffle block scan (single block, 1024 threads, 20 elems/thread)
__global__ void k_scan() {
    __shared__ int wsum[32];
    int t = threadIdx.x, lane = t & 31, wid = t >> 5;
    const int PER = 20;
    int base = t * PER;
    int s = 0;
#pragma unroll
    for (int i = 0; i < PER; i++) { int idx = base + i; if (idx < NNODE) s += g_deg[idx]; }
    int x = s;
#pragma unroll
    for (int off = 1; off < 32; off <<= 1) {
        int y = __shfl_up_sync(0xffffffffu, x, off);
        if (lane >= off) x += y;
    }
    if (lane == 31) wsum[wid] = x;
    __syncthreads();
    if (wid == 0) {
        int y = wsum[lane];
#pragma unroll
        for (int off = 1; off < 32; off <<= 1) {
            int z = __shfl_up_sync(0xffffffffu, y, off);
            if (lane >= off) y += z;
        }
        wsum[lane] = y;
    }
    __syncthreads();
    int run = x - s + (wid > 0 ? wsum[wid - 1] : 0);
#pragma unroll
    for (int i = 0; i < PER; i++) {
        int idx = base + i;
        if (idx < NNODE) {
            int v = g_deg[idx];
            g_rowoff[idx] = run;
            g_cursor[idx] = run;
            g_dis[idx] = (v > 0) ? rsqrtf((float)v) : 0.f;
            run += v;
        }
    }
}

__global__ void k_scatter(const int* __restrict__ ei) {
    int e = blockIdx.x * 256 + threadIdx.x;
    if (e >= E2) return;
    int srcv = ei[e];
    int d  = (e < NEDGE) ? ei[NEDGE + e] : ei[e - NEDGE];
    int ea = (e < NEDGE) ? e : e - NEDGE;
    int slot = atomicAdd(&g_cursor[d], 1);
    g_csr_src[slot] = srcv;
    g_csr_ea[slot]  = ea;
}

// ---------------- mask MLP + residual: g_h0 = mlp2(mask) + x ----------------
__global__ void __launch_bounds__(128) k_maskmlp(
    const float* __restrict__ x, const float* __restrict__ mask,
    const float* __restrict__ w1, const float* __restrict__ b1,
    const float* __restrict__ w2, const float* __restrict__ b2)
{
    constexpr int T = 16;
    __shared__ __align__(16) float sM[T * NF];
    __shared__ __align__(16) float sH[T * HH];
    int tid = threadIdx.x;
    int n0 = blockIdx.x * T;
    for (int o = tid; o < T * NF; o += 128) sM[o] = mask[n0 * NF + o];
    __syncthreads();

    float acc[T];
    float bj = b1[tid];
#pragma unroll
    for (int t = 0; t < T; t++) acc[t] = bj;
#pragma unroll
    for (int i = 0; i < NF; i += 4) {
        float wa = w1[(i + 0) * HH + tid], wb = w1[(i + 1) * HH + tid];
        float wc = w1[(i + 2) * HH + tid], wd = w1[(i + 3) * HH + tid];
#pragma unroll
        for (int t = 0; t < T; t++) {
            float4 v = *reinterpret_cast<const float4*>(&sM[t * NF + i]);
            acc[t] = fmaf(v.x, wa, acc[t]); acc[t] = fmaf(v.y, wb, acc[t]);
            acc[t] = fmaf(v.z, wc, acc[t]); acc[t] = fmaf(v.w, wd, acc[t]);
        }
    }
#pragma unroll
    for (int t = 0; t < T; t++) sH[t * HH + tid] = fmaxf(acc[t], 0.f);
    __syncthreads();

    for (int o = tid; o < T * NF; o += 128) {
        int t = o >> 4, c = o & 15;
        float v = b2[c];
#pragma unroll 1
        for (int k = 0; k < HH; k += 4) {
            float4 h = *reinterpret_cast<const float4*>(&sH[t * HH + k]);
            v = fmaf(h.x, w2[(k + 0) * NF + c], v);
            v = fmaf(h.y, w2[(k + 1) * NF + c], v);
            v = fmaf(h.z, w2[(k + 2) * NF + c], v);
            v = fmaf(h.w, w2[(k + 3) * NF + c], v);
        }
        g_h0[n0 * NF + o] = v + x[n0 * NF + o];
    }
}

// ---------------- GEMM: out[M,128] = op(in[M,K] @ W[K,128])  (scalar FFMA) ----
// BIASMODE: 0 = none, 1 = +bias, 2 = +deg[n]*bias.
template <int K, int BIASMODE, bool RELU>
__global__ void __launch_bounds__(128) k_mm(
    int insel, const float* __restrict__ in_ext,
    float* __restrict__ outp,
    const float* __restrict__ W, const float* __restrict__ bias)
{
    constexpr int T = 16;
    __shared__ __align__(16) float sIn[T * K];
    const float* in = sel_in(insel, in_ext);
    int tid = threadIdx.x;
    int j = tid;
    int n0 = blockIdx.x * T;

    const float4* gsrc = reinterpret_cast<const float4*>(in + (size_t)n0 * K);
    float4* ssrc = reinterpret_cast<float4*>(sIn);
    for (int o = tid; o < T * K / 4; o += 128) ssrc[o] = gsrc[o];
    __syncthreads();

    float acc[T];
    if (BIASMODE == 1) {
        float b = bias[j];
#pragma unroll
        for (int t = 0; t < T; t++) acc[t] = b;
    } else {
#pragma unroll
        for (int t = 0; t < T; t++) acc[t] = 0.f;
    }

#pragma unroll 1
    for (int k = 0; k < K; k += 4) {
        float wa = W[(k + 0) * HH + j], wb = W[(k + 1) * HH + j];
        float wc = W[(k + 2) * HH + j], wd = W[(k + 3) * HH + j];
#pragma unroll
        for (int t = 0; t < T; t++) {
            float4 v = *reinterpret_cast<const float4*>(&sIn[t * K + k]);
            acc[t] = fmaf(v.x, wa, acc[t]); acc[t] = fmaf(v.y, wb, acc[t]);
            acc[t] = fmaf(v.z, wc, acc[t]); acc[t] = fmaf(v.w, wd, acc[t]);
        }
    }

    float bscale = (BIASMODE == 2) ? bias[j] : 0.f;
#pragma unroll
    for (int t = 0; t < T; t++) {
        float v = acc[t];
        if (BIASMODE == 2) v += bscale * (float)g_deg[n0 + t];
        if (RELU) v = fmaxf(v, 0.f);
        outp[(size_t)(n0 + t) * HH + j] = v;
    }
}

// ---------------- fused TAG GEMM: nb4 = relu([h0|h1|h2|h3] @ tagw[0..3] + b) ----
__global__ void __launch_bounds__(128) k_mmTAG(
    const float* __restrict__ tagw, const float* __restrict__ tagb)
{
    constexpr int T = 16, K = 512;
    __shared__ __align__(16) float sIn[T * K];   // 32 KB
    int tid = threadIdx.x;
    int j = tid;
    int n0 = blockIdx.x * T;

    const float* bufs0 = g_nb[3];
    const float* bufs1 = g_nb[0];
    const float* bufs2 = g_nb[1];
    const float* bufs3 = g_nb[2];
    for (int o = tid; o < T * K / 4; o += 128) {
        int f = o * 4;
        int t = f >> 9;
        int seg = (f >> 7) & 3;
        int c = f & 127;
        const float* b = (seg == 0) ? bufs0 : (seg == 1) ? bufs1 : (seg == 2) ? bufs2 : bufs3;
        reinterpret_cast<float4*>(sIn)[o] =
            *reinterpret_cast<const float4*>(&b[(size_t)(n0 + t) * HH + c]);
    }
    __syncthreads();

    float acc[T];
    float bj = tagb[j];
#pragma unroll
    for (int t = 0; t < T; t++) acc[t] = bj;

#pragma unroll 1
    for (int k = 0; k < K; k += 4) {
        float wa = tagw[(k + 0) * HH + j], wb = tagw[(k + 1) * HH + j];
        float wc = tagw[(k + 2) * HH + j], wd = tagw[(k + 3) * HH + j];
#pragma unroll
        for (int t = 0; t < T; t++) {
            float4 v = *reinterpret_cast<const float4*>(&sIn[t * K + k]);
            acc[t] = fmaf(v.x, wa, acc[t]); acc[t] = fmaf(v.y, wb, acc[t]);
            acc[t] = fmaf(v.z, wc, acc[t]); acc[t] = fmaf(v.w, wd, acc[t]);
        }
    }
#pragma unroll
    for (int t = 0; t < T; t++)
        g_nb[4][(size_t)(n0 + t) * HH + j] = fmaxf(acc[t], 0.f);
}

// ---------------- fused hidden + aggregation ----------------
// S[n] = sum over incident edges of relu(A[n] + B[src] + C[ea])
__global__ void k_fused_agg(int msel) {
    const float* __restrict__ A = g_nb[0];
    const float* __restrict__ B = g_nb[1];
    const float* __restrict__ M = g_msg[msel];
    float* __restrict__ S = g_nb[2];
    int n = blockIdx.x, j = threadIdx.x;
    int beg = g_rowoff[n], len = g_deg[n];
    float a = A[(size_t)n * HH + j];
    float acc = 0.f;
    for (int i = 0; i < len; i++) {
        int s  = __ldg(&g_csr_src[beg + i]);
        int ea = __ldg(&g_csr_ea[beg + i]);
        acc += fmaxf(a + __ldg(&B[(size_t)s * HH + j]) + __ldg(&M[(size_t)ea * HH + j]), 0.f);
    }
    S[(size_t)n * HH + j] = acc;
}

// ---------------- TAG propagation hop: out[n] = dis[n] * sum dis[s] * h[s] ----------------
__global__ void k_hop(int insel, int outsel) {
    const float* __restrict__ hin = g_nb[insel];
    float* __restrict__ hout = g_nb[outsel];
    int n = blockIdx.x, j = threadIdx.x;
    int beg = g_rowoff[n], len = g_deg[n];
    float acc = 0.f;
    for (int i = 0; i < len; i++) {
        int s = __ldg(&g_csr_src[beg + i]);
        acc = fmaf(__ldg(&g_dis[s]), __ldg(&hin[(size_t)s * HH + j]), acc);
    }
    hout[(size_t)n * HH + j] = g_dis[n] * acc;
}

// ---------------- final: out[n,16] = S[n]@W2[128,16] + deg[n]*b2 ----------------
__global__ void __launch_bounds__(128) k_out16(
    float* __restrict__ out, const float* __restrict__ W2, const float* __restrict__ b2)
{
    int tid = threadIdx.x;
    int n = blockIdx.x * 8 + (tid >> 4);
    int c = tid & 15;
    const float* S = g_nb[2];
    float acc = b2[c] * (float)g_deg[n];
#pragma unroll 4
    for (int k = 0; k < HH; k++)
        acc = fmaf(__ldg(&S[(size_t)n * HH + k]), __ldg(&W2[k * 16 + c]), acc);
    out[n * 16 + c] = acc;
}

// ---------------- launch ----------------
extern "C" void kernel_launch(void* const* d_in, const int* in_sizes, int n_in,
                              void* d_out, int out_size)
{
    static const int ESZ[24] = {
        320000, 320000, 2560000, 320000,
        2048, 128, 2048, 16,
        6144, 128, 16384, 128,
        65536, 128,
        34816, 128, 16384, 128,
        65536, 128,
        34816, 128, 2048, 16};
    static const int M_DICT[24] = {0,1,2,3,4,5,6,7,8,9,10,11,12,13,14,15,16,17,18,19,20,21,22,23};
    static const int M_SIG[24]  = {0,1,2,23,3,4,5,6,7,8,9,10,11,12,13,14,15,16,17,18,19,20,21,22};
    static const int M_ALPHA[24]= {23,18,12,13,16,14,17,15,2,0,3,1,20,19,6,4,7,5,22,21,10,8,11,9};
    const int* cands[3] = {M_DICT, M_SIG, M_ALPHA};
    const int* map = M_DICT;
    for (int ci = 0; ci < 3; ci++) {
        bool ok = (n_in >= 24);
        for (int l = 0; l < 24 && ok; l++) ok = (in_sizes[cands[ci][l]] == ESZ[l]);
        if (ok) { map = cands[ci]; break; }
    }
#define INP(l) ((const float*)d_in[map[l]])
    const float* x     = INP(0);
    const float* mask  = INP(1);
    const float* eattr = INP(2);
    const int*   ei    = (const int*)d_in[map[3]];
    const float *m_w1 = INP(4), *m_b1 = INP(5), *m_w2 = INP(6), *m_b2 = INP(7);
    const float *ea0w1 = INP(8), *ea0b1 = INP(9), *ea0w2 = INP(10), *ea0b2 = INP(11);
    const float *tag0w = INP(12), *tag0b = INP(13);
    const float *ea1w1 = INP(14), *ea1b1 = INP(15), *ea1w2 = INP(16), *ea1b2 = INP(17);
    const float *tag1w = INP(18), *tag1b = INP(19);
    const float *ea2w1 = INP(20), *ea2b1 = INP(21), *ea2w2 = INP(22), *ea2b2 = INP(23);
#undef INP
    float* out = (float*)d_out;
    (void)out_size;

    const int GN = NNODE / 16;   // 1250 node-GEMM blocks
    const int GE = NEDGE / 16;   // 10000 edge-C blocks

    // one-time host-side resources (address queries + stream/event creation only)
    static float* s_nb[5] = {nullptr, nullptr, nullptr, nullptr, nullptr};
    static float* s_msg[3] = {nullptr, nullptr, nullptr};
    static cudaStream_t s1 = nullptr, s2 = nullptr;
    static cudaEvent_t evFork = nullptr, evS1 = nullptr, evS2 = nullptr;
    static cudaEvent_t evT0 = nullptr, evC1 = nullptr, evT1 = nullptr, evC2 = nullptr;
    if (!s_nb[0]) {
        void* p = nullptr;
        cudaGetSymbolAddress(&p, g_nb);
        for (int i = 0; i < 5; i++) s_nb[i] = (float*)p + (size_t)i * NNODE * HH;
        cudaGetSymbolAddress(&p, g_msg);
        for (int i = 0; i < 3; i++) s_msg[i] = (float*)p + (size_t)i * NEDGE * HH;
        cudaStreamCreateWithFlags(&s1, cudaStreamNonBlocking);
        cudaStreamCreateWithFlags(&s2, cudaStreamNonBlocking);
        cudaEventCreateWithFlags(&evFork, cudaEventDisableTiming);
        cudaEventCreateWithFlags(&evS1, cudaEventDisableTiming);
        cudaEventCreateWithFlags(&evS2, cudaEventDisableTiming);
        cudaEventCreateWithFlags(&evT0, cudaEventDisableTiming);
        cudaEventCreateWithFlags(&evC1, cudaEventDisableTiming);
        cudaEventCreateWithFlags(&evT1, cudaEventDisableTiming);
        cudaEventCreateWithFlags(&evC2, cudaEventDisableTiming);
    }

    // ---- fork: CSR build on main; node GEMMs on s1; layer-0 C GEMM on s2 ----
    cudaEventRecord(evFork, 0);
    cudaStreamWaitEvent(s1, evFork, 0);
    cudaStreamWaitEvent(s2, evFork, 0);

    k_zero<<<(NNODE + 255) / 256, 256>>>();
    k_hist<<<E2 / 256, 256>>>(ei);
    k_scan<<<1, 1024>>>();
    k_scatter<<<E2 / 256, 256>>>(ei);

    k_maskmlp<<<GN, 128, 0, s1>>>(x, mask, m_w1, m_b1, m_w2, m_b2);
    k_mm<16, 1, false><<<GN, 128, 0, s1>>>(-3, nullptr, s_nb[0], ea0w1,           ea0b1);
    k_mm<16, 0, false><<<GN, 128, 0, s1>>>(-3, nullptr, s_nb[1], ea0w1 + 16 * HH, nullptr);

    k_mm<16, 0, false><<<GE, 128, 0, s2>>>(-1, eattr, s_msg[0], ea0w1 + 32 * HH, nullptr);

    cudaEventRecord(evS1, s1);
    cudaEventRecord(evS2, s2);
    cudaStreamWaitEvent(0, evS1, 0);
    cudaStreamWaitEvent(0, evS2, 0);

    // ---- EA0: agg; layer-2 -> nb3 ----
    k_fused_agg<<<NNODE, 128>>>(0);
    k_mm<128, 2, true><<<GN, 128>>>(2, nullptr, s_nb[3], ea0w2, ea0b2);

    // ---- TAG0 (hops are L2-bound): overlap layer-1 C GEMM (FMA-bound) on s2 ----
    cudaEventRecord(evT0, 0);
    cudaStreamWaitEvent(s2, evT0, 0);
    k_mm<16, 0, false><<<GE, 128, 0, s2>>>(-1, eattr, s_msg[1], ea1w1 + 256 * HH, nullptr);
    cudaEventRecord(evC1, s2);

    k_hop<<<NNODE, 128>>>(3, 0);
    k_hop<<<NNODE, 128>>>(0, 1);
    k_hop<<<NNODE, 128>>>(1, 2);
    k_mmTAG<<<GN, 128>>>(tag0w, tag0b);

    // ---- EA1 (nb4 -> 128) -> nb3 ----
    k_mm<128, 1, false><<<GN, 128>>>(4, nullptr, s_nb[0], ea1w1,            ea1b1);
    k_mm<128, 0, false><<<GN, 128>>>(4, nullptr, s_nb[1], ea1w1 + 128 * HH, nullptr);
    cudaStreamWaitEvent(0, evC1, 0);
    k_fused_agg<<<NNODE, 128>>>(1);
    k_mm<128, 2, true><<<GN, 128>>>(2, nullptr, s_nb[3], ea1w2, ea1b2);

    // ---- TAG1: overlap layer-2 C GEMM on s2 ----
    cudaEventRecord(evT1, 0);
    cudaStreamWaitEvent(s2, evT1, 0);
    k_mm<16, 0, false><<<GE, 128, 0, s2>>>(-1, eattr, s_msg[2], ea2w1 + 256 * HH, nullptr);
    cudaEventRecord(evC2, s2);

    k_hop<<<NNODE, 128>>>(3, 0);
    k_hop<<<NNODE, 128>>>(0, 1);
    k_hop<<<NNODE, 128>>>(1, 2);
    k_mmTAG<<<GN, 128>>>(tag1w, tag1b);

    // ---- EA2 (nb4 -> 16) -> d_out ----
    k_mm<128, 1, false><<<GN, 128>>>(4, nullptr, s_nb[0], ea2w1,            ea2b1);
    k_mm<128, 0, false><<<GN, 128>>>(4, nullptr, s_nb[1], ea2w1 + 128 * HH, nullptr);
    cudaStreamWaitEvent(0, evC2, 0);
    k_fused_agg<<<NNODE, 128>>>(2);
    k_out16<<<NNODE / 8, 128>>>(out, ea2w2, ea2b2);
}

// round 9
// speedup vs baseline: 1.1833x; 1.1161x over previous
#include <cuda_runtime.h>
#include <math.h>

#define NNODE 20000
#define NEDGE 160000
#define E2    320000
#define HH    128
#define NF    16
#define EF    16

// ---------------- device scratch (no allocations allowed) ----------------
__device__ int   g_deg[NNODE];
__device__ int   g_rowoff[NNODE];
__device__ int   g_cursor[NNODE];
__device__ float g_dis[NNODE];
__device__ int   g_csr_src[E2];
__device__ int   g_csr_ea[E2];                 // eattr index (0..NEDGE)
__device__ float g_h0[NNODE * NF];
__device__ float g_nb[5][NNODE * HH];          // node-feature buffers
__device__ float g_msg[3][(size_t)NEDGE * HH]; // per-unique-edge C buffers

__device__ __forceinline__ const float* sel_in(int s, const float* ext) {
    if (s >= 0) return g_nb[s];
    if (s == -3) return g_h0;
    return ext;
}

// ---------------- graph structure build ----------------
__global__ void k_zero() {
    int i = blockIdx.x * 256 + threadIdx.x;
    if (i < NNODE) g_deg[i] = 0;
}

__global__ void k_hist(const int* __restrict__ ei) {
    int e = blockIdx.x * 256 + threadIdx.x;
    if (e >= E2) return;
    int d = (e < NEDGE) ? ei[NEDGE + e] : ei[e - NEDGE];
    atomicAdd(&g_deg[d], 1);
}

// warp-shuffle block scan (single block, 1024 threads, 20 elems/thread)
__global__ void k_scan() {
    __shared__ int wsum[32];
    int t = threadIdx.x, lane = t & 31, wid = t >> 5;
    const int PER = 20;
    int base = t * PER;
    int s = 0;
#pragma unroll
    for (int i = 0; i < PER; i++) { int idx = base + i; if (idx < NNODE) s += g_deg[idx]; }
    int x = s;
#pragma unroll
    for (int off = 1; off < 32; off <<= 1) {
        int y = __shfl_up_sync(0xffffffffu, x, off);
        if (lane >= off) x += y;
    }
    if (lane == 31) wsum[wid] = x;
    __syncthreads();
    if (wid == 0) {
        int y = wsum[lane];
#pragma unroll
        for (int off = 1; off < 32; off <<= 1) {
            int z = __shfl_up_sync(0xffffffffu, y, off);
            if (lane >= off) y += z;
        }
        wsum[lane] = y;
    }
    __syncthreads();
    int run = x - s + (wid > 0 ? wsum[wid - 1] : 0);
#pragma unroll
    for (int i = 0; i < PER; i++) {
        int idx = base + i;
        if (idx < NNODE) {
            int v = g_deg[idx];
            g_rowoff[idx] = run;
            g_cursor[idx] = run;
            g_dis[idx] = (v > 0) ? rsqrtf((float)v) : 0.f;
            run += v;
        }
    }
}

__global__ void k_scatter(const int* __restrict__ ei) {
    int e = blockIdx.x * 256 + threadIdx.x;
    if (e >= E2) return;
    int srcv = ei[e];
    int d  = (e < NEDGE) ? ei[NEDGE + e] : ei[e - NEDGE];
    int ea = (e < NEDGE) ? e : e - NEDGE;
    int slot = atomicAdd(&g_cursor[d], 1);
    g_csr_src[slot] = srcv;
    g_csr_ea[slot]  = ea;
}

// ---------------- mask MLP + residual: g_h0 = mlp2(mask) + x ----------------
__global__ void __launch_bounds__(128) k_maskmlp(
    const float* __restrict__ x, const float* __restrict__ mask,
    const float* __restrict__ w1, const float* __restrict__ b1,
    const float* __restrict__ w2, const float* __restrict__ b2)
{
    constexpr int T = 16;
    __shared__ __align__(16) float sM[T * NF];
    __shared__ __align__(16) float sH[T * HH];
    int tid = threadIdx.x;
    int n0 = blockIdx.x * T;
    for (int o = tid; o < T * NF; o += 128) sM[o] = mask[n0 * NF + o];
    __syncthreads();

    float acc[T];
    float bj = b1[tid];
#pragma unroll
    for (int t = 0; t < T; t++) acc[t] = bj;
#pragma unroll
    for (int i = 0; i < NF; i += 4) {
        float wa = w1[(i + 0) * HH + tid], wb = w1[(i + 1) * HH + tid];
        float wc = w1[(i + 2) * HH + tid], wd = w1[(i + 3) * HH + tid];
#pragma unroll
        for (int t = 0; t < T; t++) {
            float4 v = *reinterpret_cast<const float4*>(&sM[t * NF + i]);
            acc[t] = fmaf(v.x, wa, acc[t]); acc[t] = fmaf(v.y, wb, acc[t]);
            acc[t] = fmaf(v.z, wc, acc[t]); acc[t] = fmaf(v.w, wd, acc[t]);
        }
    }
#pragma unroll
    for (int t = 0; t < T; t++) sH[t * HH + tid] = fmaxf(acc[t], 0.f);
    __syncthreads();

    for (int o = tid; o < T * NF; o += 128) {
        int t = o >> 4, c = o & 15;
        float v = b2[c];
#pragma unroll 1
        for (int k = 0; k < HH; k += 4) {
            float4 h = *reinterpret_cast<const float4*>(&sH[t * HH + k]);
            v = fmaf(h.x, w2[(k + 0) * NF + c], v);
            v = fmaf(h.y, w2[(k + 1) * NF + c], v);
            v = fmaf(h.z, w2[(k + 2) * NF + c], v);
            v = fmaf(h.w, w2[(k + 3) * NF + c], v);
        }
        g_h0[n0 * NF + o] = v + x[n0 * NF + o];
    }
}

// ---------------- GEMM: out[M,128] = op(in[M,K] @ W[K,128])  T=32 rows/block ----
// BIASMODE: 0 = none, 1 = +bias, 2 = +deg[n]*bias.
template <int K, int BIASMODE, bool RELU>
__global__ void __launch_bounds__(128) k_mm(
    int insel, const float* __restrict__ in_ext,
    float* __restrict__ outp,
    const float* __restrict__ W, const float* __restrict__ bias)
{
    constexpr int T = 32;
    __shared__ __align__(16) float sIn[T * K];
    const float* in = sel_in(insel, in_ext);
    int tid = threadIdx.x;
    int j = tid;
    int n0 = blockIdx.x * T;

    const float4* gsrc = reinterpret_cast<const float4*>(in + (size_t)n0 * K);
    float4* ssrc = reinterpret_cast<float4*>(sIn);
    for (int o = tid; o < T * K / 4; o += 128) ssrc[o] = gsrc[o];
    __syncthreads();

    float acc[T];
    if (BIASMODE == 1) {
        float b = bias[j];
#pragma unroll
        for (int t = 0; t < T; t++) acc[t] = b;
    } else {
#pragma unroll
        for (int t = 0; t < T; t++) acc[t] = 0.f;
    }

#pragma unroll 1
    for (int k = 0; k < K; k += 4) {
        float wa = W[(k + 0) * HH + j], wb = W[(k + 1) * HH + j];
        float wc = W[(k + 2) * HH + j], wd = W[(k + 3) * HH + j];
#pragma unroll
        for (int t = 0; t < T; t++) {
            float4 v = *reinterpret_cast<const float4*>(&sIn[t * K + k]);
            acc[t] = fmaf(v.x, wa, acc[t]); acc[t] = fmaf(v.y, wb, acc[t]);
            acc[t] = fmaf(v.z, wc, acc[t]); acc[t] = fmaf(v.w, wd, acc[t]);
        }
    }

    float bscale = (BIASMODE == 2) ? bias[j] : 0.f;
#pragma unroll
    for (int t = 0; t < T; t++) {
        float v = acc[t];
        if (BIASMODE == 2) v += bscale * (float)g_deg[n0 + t];
        if (RELU) v = fmaxf(v, 0.f);
        outp[(size_t)(n0 + t) * HH + j] = v;
    }
}

// ---------------- twin GEMM via gridDim.y: y=0 -> nb0 (WA,+biasA); y=1 -> nb1 (WB) ----
template <int K>
__global__ void __launch_bounds__(128) k_mm2(
    int insel, const float* __restrict__ in_ext,
    const float* __restrict__ WA, const float* __restrict__ biasA,
    const float* __restrict__ WB)
{
    constexpr int T = 32;
    __shared__ __align__(16) float sIn[T * K];
    const float* in = sel_in(insel, in_ext);
    int tid = threadIdx.x;
    int j = tid;
    int n0 = blockIdx.x * T;
    bool isA = (blockIdx.y == 0);
    const float* W = isA ? WA : WB;
    float* outp = g_nb[isA ? 0 : 1];

    const float4* gsrc = reinterpret_cast<const float4*>(in + (size_t)n0 * K);
    float4* ssrc = reinterpret_cast<float4*>(sIn);
    for (int o = tid; o < T * K / 4; o += 128) ssrc[o] = gsrc[o];
    __syncthreads();

    float acc[T];
    float b = isA ? biasA[j] : 0.f;
#pragma unroll
    for (int t = 0; t < T; t++) acc[t] = b;

#pragma unroll 1
    for (int k = 0; k < K; k += 4) {
        float wa = W[(k + 0) * HH + j], wb = W[(k + 1) * HH + j];
        float wc = W[(k + 2) * HH + j], wd = W[(k + 3) * HH + j];
#pragma unroll
        for (int t = 0; t < T; t++) {
            float4 v = *reinterpret_cast<const float4*>(&sIn[t * K + k]);
            acc[t] = fmaf(v.x, wa, acc[t]); acc[t] = fmaf(v.y, wb, acc[t]);
            acc[t] = fmaf(v.z, wc, acc[t]); acc[t] = fmaf(v.w, wd, acc[t]);
        }
    }
#pragma unroll
    for (int t = 0; t < T; t++)
        outp[(size_t)(n0 + t) * HH + j] = acc[t];
}

// ---------------- fused TAG GEMM: nb4 = relu([h0|h1|h2|h3] @ tagw[0..3] + b) ----
__global__ void __launch_bounds__(128) k_mmTAG(
    const float* __restrict__ tagw, const float* __restrict__ tagb)
{
    constexpr int T = 16, K = 512;
    __shared__ __align__(16) float sIn[T * K];   // 32 KB
    int tid = threadIdx.x;
    int j = tid;
    int n0 = blockIdx.x * T;

    const float* bufs0 = g_nb[3];
    const float* bufs1 = g_nb[0];
    const float* bufs2 = g_nb[1];
    const float* bufs3 = g_nb[2];
    for (int o = tid; o < T * K / 4; o += 128) {
        int f = o * 4;
        int t = f >> 9;
        int seg = (f >> 7) & 3;
        int c = f & 127;
        const float* b = (seg == 0) ? bufs0 : (seg == 1) ? bufs1 : (seg == 2) ? bufs2 : bufs3;
        reinterpret_cast<float4*>(sIn)[o] =
            *reinterpret_cast<const float4*>(&b[(size_t)(n0 + t) * HH + c]);
    }
    __syncthreads();

    float acc[T];
    float bj = tagb[j];
#pragma unroll
    for (int t = 0; t < T; t++) acc[t] = bj;

#pragma unroll 1
    for (int k = 0; k < K; k += 4) {
        float wa = tagw[(k + 0) * HH + j], wb = tagw[(k + 1) * HH + j];
        float wc = tagw[(k + 2) * HH + j], wd = tagw[(k + 3) * HH + j];
#pragma unroll
        for (int t = 0; t < T; t++) {
            float4 v = *reinterpret_cast<const float4*>(&sIn[t * K + k]);
            acc[t] = fmaf(v.x, wa, acc[t]); acc[t] = fmaf(v.y, wb, acc[t]);
            acc[t] = fmaf(v.z, wc, acc[t]); acc[t] = fmaf(v.w, wd, acc[t]);
        }
    }
#pragma unroll
    for (int t = 0; t < T; t++)
        g_nb[4][(size_t)(n0 + t) * HH + j] = fmaxf(acc[t], 0.f);
}

// ---------------- fused hidden + aggregation (warp per node, float4 lanes) ----
// S[n] = sum over incident edges of relu(A[n] + B[src] + C[ea])
__global__ void __launch_bounds__(256) k_fused_agg(int msel) {
    const float4* __restrict__ A = reinterpret_cast<const float4*>(g_nb[0]);
    const float4* __restrict__ B = reinterpret_cast<const float4*>(g_nb[1]);
    const float4* __restrict__ M = reinterpret_cast<const float4*>(g_msg[msel]);
    float4* __restrict__ S = reinterpret_cast<float4*>(g_nb[2]);
    int lane = threadIdx.x & 31;
    int n = blockIdx.x * 8 + (threadIdx.x >> 5);
    if (n >= NNODE) return;
    int beg = g_rowoff[n], len = g_deg[n];
    float4 a = A[(size_t)n * 32 + lane];
    float4 acc = make_float4(0.f, 0.f, 0.f, 0.f);
    for (int i = 0; i < len; i++) {
        int s  = __ldg(&g_csr_src[beg + i]);
        int ea = __ldg(&g_csr_ea[beg + i]);
        float4 b = __ldg(&B[(size_t)s * 32 + lane]);
        float4 m = __ldg(&M[(size_t)ea * 32 + lane]);
        acc.x += fmaxf(a.x + b.x + m.x, 0.f);
        acc.y += fmaxf(a.y + b.y + m.y, 0.f);
        acc.z += fmaxf(a.z + b.z + m.z, 0.f);
        acc.w += fmaxf(a.w + b.w + m.w, 0.f);
    }
    S[(size_t)n * 32 + lane] = acc;
}

// ---------------- TAG hop (warp per node, float4 lanes) ----------------
// out[n] = dis[n] * sum dis[s] * h[s]
__global__ void __launch_bounds__(256) k_hop(int insel, int outsel) {
    const float4* __restrict__ hin = reinterpret_cast<const float4*>(g_nb[insel]);
    float4* __restrict__ hout = reinterpret_cast<float4*>(g_nb[outsel]);
    int lane = threadIdx.x & 31;
    int n = blockIdx.x * 8 + (threadIdx.x >> 5);
    if (n >= NNODE) return;
    int beg = g_rowoff[n], len = g_deg[n];
    float4 acc = make_float4(0.f, 0.f, 0.f, 0.f);
    for (int i = 0; i < len; i++) {
        int s = __ldg(&g_csr_src[beg + i]);
        float d = __ldg(&g_dis[s]);
        float4 h = __ldg(&hin[(size_t)s * 32 + lane]);
        acc.x = fmaf(d, h.x, acc.x);
        acc.y = fmaf(d, h.y, acc.y);
        acc.z = fmaf(d, h.z, acc.z);
        acc.w = fmaf(d, h.w, acc.w);
    }
    float dn = g_dis[n];
    acc.x *= dn; acc.y *= dn; acc.z *= dn; acc.w *= dn;
    hout[(size_t)n * 32 + lane] = acc;
}

// ---------------- final: out[n,16] = S[n]@W2[128,16] + deg[n]*b2 ----------------
__global__ void __launch_bounds__(128) k_out16(
    float* __restrict__ out, const float* __restrict__ W2, const float* __restrict__ b2)
{
    int tid = threadIdx.x;
    int n = blockIdx.x * 8 + (tid >> 4);
    int c = tid & 15;
    const float* S = g_nb[2];
    float acc = b2[c] * (float)g_deg[n];
#pragma unroll 4
    for (int k = 0; k < HH; k++)
        acc = fmaf(__ldg(&S[(size_t)n * HH + k]), __ldg(&W2[k * 16 + c]), acc);
    out[n * 16 + c] = acc;
}

// ---------------- launch ----------------
extern "C" void kernel_launch(void* const* d_in, const int* in_sizes, int n_in,
                              void* d_out, int out_size)
{
    static const int ESZ[24] = {
        320000, 320000, 2560000, 320000,
        2048, 128, 2048, 16,
        6144, 128, 16384, 128,
        65536, 128,
        34816, 128, 16384, 128,
        65536, 128,
        34816, 128, 2048, 16};
    static const int M_DICT[24] = {0,1,2,3,4,5,6,7,8,9,10,11,12,13,14,15,16,17,18,19,20,21,22,23};
    static const int M_SIG[24]  = {0,1,2,23,3,4,5,6,7,8,9,10,11,12,13,14,15,16,17,18,19,20,21,22};
    static const int M_ALPHA[24]= {23,18,12,13,16,14,17,15,2,0,3,1,20,19,6,4,7,5,22,21,10,8,11,9};
    const int* cands[3] = {M_DICT, M_SIG, M_ALPHA};
    const int* map = M_DICT;
    for (int ci = 0; ci < 3; ci++) {
        bool ok = (n_in >= 24);
        for (int l = 0; l < 24 && ok; l++) ok = (in_sizes[cands[ci][l]] == ESZ[l]);
        if (ok) { map = cands[ci]; break; }
    }
#define INP(l) ((const float*)d_in[map[l]])
    const float* x     = INP(0);
    const float* mask  = INP(1);
    const float* eattr = INP(2);
    const int*   ei    = (const int*)d_in[map[3]];
    const float *m_w1 = INP(4), *m_b1 = INP(5), *m_w2 = INP(6), *m_b2 = INP(7);
    const float *ea0w1 = INP(8), *ea0b1 = INP(9), *ea0w2 = INP(10), *ea0b2 = INP(11);
    const float *tag0w = INP(12), *tag0b = INP(13);
    const float *ea1w1 = INP(14), *ea1b1 = INP(15), *ea1w2 = INP(16), *ea1b2 = INP(17);
    const float *tag1w = INP(18), *tag1b = INP(19);
    const float *ea2w1 = INP(20), *ea2b1 = INP(21), *ea2w2 = INP(22), *ea2b2 = INP(23);
#undef INP
    float* out = (float*)d_out;
    (void)out_size;

    const int GN32 = NNODE / 32;   // 625  (T=32 node GEMMs)
    const int GN16 = NNODE / 16;   // 1250 (T=16: maskmlp, mmTAG)
    const int GE32 = NEDGE / 32;   // 5000 (T=32 edge-C GEMM)
    const int GW   = NNODE / 8;    // 2500 (warp-per-node gathers, 8 warps/block)

    // one-time host-side resources (address queries + stream/event creation only)
    static float* s_nb[5] = {nullptr, nullptr, nullptr, nullptr, nullptr};
    static float* s_msg[3] = {nullptr, nullptr, nullptr};
    static cudaStream_t s1 = nullptr, s2 = nullptr;
    static cudaEvent_t evFork = nullptr, evS1 = nullptr, evS2 = nullptr;
    static cudaEvent_t evT0 = nullptr, evC1 = nullptr, evT1 = nullptr, evC2 = nullptr;
    if (!s_nb[0]) {
        void* p = nullptr;
        cudaGetSymbolAddress(&p, g_nb);
        for (int i = 0; i < 5; i++) s_nb[i] = (float*)p + (size_t)i * NNODE * HH;
        cudaGetSymbolAddress(&p, g_msg);
        for (int i = 0; i < 3; i++) s_msg[i] = (float*)p + (size_t)i * NEDGE * HH;
        cudaStreamCreateWithFlags(&s1, cudaStreamNonBlocking);
        cudaStreamCreateWithFlags(&s2, cudaStreamNonBlocking);
        cudaEventCreateWithFlags(&evFork, cudaEventDisableTiming);
        cudaEventCreateWithFlags(&evS1, cudaEventDisableTiming);
        cudaEventCreateWithFlags(&evS2, cudaEventDisableTiming);
        cudaEventCreateWithFlags(&evT0, cudaEventDisableTiming);
        cudaEventCreateWithFlags(&evC1, cudaEventDisableTiming);
        cudaEventCreateWithFlags(&evT1, cudaEventDisableTiming);
        cudaEventCreateWithFlags(&evC2, cudaEventDisableTiming);
    }

    // ---- fork: CSR build on main; node GEMMs on s1; layer-0 C GEMM on s2 ----
    cudaEventRecord(evFork, 0);
    cudaStreamWaitEvent(s1, evFork, 0);
    cudaStreamWaitEvent(s2, evFork, 0);

    k_zero<<<(NNODE + 255) / 256, 256>>>();
    k_hist<<<E2 / 256, 256>>>(ei);
    k_scan<<<1, 1024>>>();
    k_scatter<<<E2 / 256, 256>>>(ei);

    k_maskmlp<<<GN16, 128, 0, s1>>>(x, mask, m_w1, m_b1, m_w2, m_b2);
    k_mm2<16><<<dim3(GN32, 2), 128, 0, s1>>>(-3, nullptr, ea0w1, ea0b1, ea0w1 + 16 * HH);

    k_mm<16, 0, false><<<GE32, 128, 0, s2>>>(-1, eattr, s_msg[0], ea0w1 + 32 * HH, nullptr);

    cudaEventRecord(evS1, s1);
    cudaEventRecord(evS2, s2);
    cudaStreamWaitEvent(0, evS1, 0);
    cudaStreamWaitEvent(0, evS2, 0);

    // ---- EA0: agg; layer-2 -> nb3 ----
    k_fused_agg<<<GW, 256>>>(0);
    k_mm<128, 2, true><<<GN32, 128>>>(2, nullptr, s_nb[3], ea0w2, ea0b2);

    // ---- TAG0 (hops are L2-bound): overlap layer-1 C GEMM (FMA-bound) on s2 ----
    cudaEventRecord(evT0, 0);
    cudaStreamWaitEvent(s2, evT0, 0);
    k_mm<16, 0, false><<<GE32, 128, 0, s2>>>(-1, eattr, s_msg[1], ea1w1 + 256 * HH, nullptr);
    cudaEventRecord(evC1, s2);

    k_hop<<<GW, 256>>>(3, 0);
    k_hop<<<GW, 256>>>(0, 1);
    k_hop<<<GW, 256>>>(1, 2);
    k_mmTAG<<<GN16, 128>>>(tag0w, tag0b);

    // ---- EA1 (nb4 -> 128) -> nb3 ----
    k_mm2<128><<<dim3(GN32, 2), 128>>>(4, nullptr, ea1w1, ea1b1, ea1w1 + 128 * HH);
    cudaStreamWaitEvent(0, evC1, 0);
    k_fused_agg<<<GW, 256>>>(1);
    k_mm<128, 2, true><<<GN32, 128>>>(2, nullptr, s_nb[3], ea1w2, ea1b2);

    // ---- TAG1: overlap layer-2 C GEMM on s2 ----
    cudaEventRecord(evT1, 0);
    cudaStreamWaitEvent(s2, evT1, 0);
    k_mm<16, 0, false><<<GE32, 128, 0, s2>>>(-1, eattr, s_msg[2], ea2w1 + 256 * HH, nullptr);
    cudaEventRecord(evC2, s2);

    k_hop<<<GW, 256>>>(3, 0);
    k_hop<<<GW, 256>>>(0, 1);
    k_hop<<<GW, 256>>>(1, 2);
    k_mmTAG<<<GN16, 128>>>(tag1w, tag1b);

    // ---- EA2 (nb4 -> 16) -> d_out ----
    k_mm2<128><<<dim3(GN32, 2), 128>>>(4, nullptr, ea2w1, ea2b1, ea2w1 + 128 * HH);
    cudaStreamWaitEvent(0, evC2, 0);
    k_fused_agg<<<GW, 256>>>(2);
    k_out16<<<NNODE / 8, 128>>>(out, ea2w2, ea2b2);
}

// round 10
// speedup vs baseline: 1.3499x; 1.1408x over previous
#include <cuda_runtime.h>
#include <math.h>

#define NNODE 20000
#define NEDGE 160000
#define E2    320000
#define HH    128
#define NF    16
#define EF    16

// ---------------- device scratch (no allocations allowed) ----------------
__device__ int   g_deg[NNODE];
__device__ int   g_rowoff[NNODE];
__device__ int   g_cursor[NNODE];
__device__ float g_dis[NNODE];
__device__ int   g_csr_src[E2];
__device__ int   g_csr_ea[E2];                 // eattr index (0..NEDGE)
__device__ float g_h0[NNODE * NF];
__device__ float g_nb[5][NNODE * HH];          // node-feature buffers
__device__ float g_msg[3][(size_t)NEDGE * HH]; // per-unique-edge C buffers

__device__ __forceinline__ const float* sel_in(int s, const float* ext) {
    if (s >= 0) return g_nb[s];
    if (s == -3) return g_h0;
    return ext;
}

// ---------------- graph structure build ----------------
__global__ void k_zero() {
    int i = blockIdx.x * 256 + threadIdx.x;
    if (i < NNODE) g_deg[i] = 0;
}

__global__ void k_hist(const int* __restrict__ ei) {
    int e = blockIdx.x * 256 + threadIdx.x;
    if (e >= E2) return;
    int d = (e < NEDGE) ? ei[NEDGE + e] : ei[e - NEDGE];
    atomicAdd(&g_deg[d], 1);
}

// warp-shuffle block scan (single block, 1024 threads, 20 elems/thread)
__global__ void k_scan() {
    __shared__ int wsum[32];
    int t = threadIdx.x, lane = t & 31, wid = t >> 5;
    const int PER = 20;
    int base = t * PER;
    int s = 0;
#pragma unroll
    for (int i = 0; i < PER; i++) { int idx = base + i; if (idx < NNODE) s += g_deg[idx]; }
    int x = s;
#pragma unroll
    for (int off = 1; off < 32; off <<= 1) {
        int y = __shfl_up_sync(0xffffffffu, x, off);
        if (lane >= off) x += y;
    }
    if (lane == 31) wsum[wid] = x;
    __syncthreads();
    if (wid == 0) {
        int y = wsum[lane];
#pragma unroll
        for (int off = 1; off < 32; off <<= 1) {
            int z = __shfl_up_sync(0xffffffffu, y, off);
            if (lane >= off) y += z;
        }
        wsum[lane] = y;
    }
    __syncthreads();
    int run = x - s + (wid > 0 ? wsum[wid - 1] : 0);
#pragma unroll
    for (int i = 0; i < PER; i++) {
        int idx = base + i;
        if (idx < NNODE) {
            int v = g_deg[idx];
            g_rowoff[idx] = run;
            g_cursor[idx] = run;
            g_dis[idx] = (v > 0) ? rsqrtf((float)v) : 0.f;
            run += v;
        }
    }
}

__global__ void k_scatter(const int* __restrict__ ei) {
    int e = blockIdx.x * 256 + threadIdx.x;
    if (e >= E2) return;
    int srcv = ei[e];
    int d  = (e < NEDGE) ? ei[NEDGE + e] : ei[e - NEDGE];
    int ea = (e < NEDGE) ? e : e - NEDGE;
    int slot = atomicAdd(&g_cursor[d], 1);
    g_csr_src[slot] = srcv;
    g_csr_ea[slot]  = ea;
}

// ---------------- mask MLP + residual: g_h0 = mlp2(mask) + x ----------------
__global__ void __launch_bounds__(128) k_maskmlp(
    const float* __restrict__ x, const float* __restrict__ mask,
    const float* __restrict__ w1, const float* __restrict__ b1,
    const float* __restrict__ w2, const float* __restrict__ b2)
{
    constexpr int T = 16;
    __shared__ __align__(16) float sM[T * NF];
    __shared__ __align__(16) float sH[T * HH];
    int tid = threadIdx.x;
    int n0 = blockIdx.x * T;
    for (int o = tid; o < T * NF; o += 128) sM[o] = mask[n0 * NF + o];
    __syncthreads();

    float acc[T];
    float bj = b1[tid];
#pragma unroll
    for (int t = 0; t < T; t++) acc[t] = bj;
#pragma unroll
    for (int i = 0; i < NF; i += 4) {
        float wa = w1[(i + 0) * HH + tid], wb = w1[(i + 1) * HH + tid];
        float wc = w1[(i + 2) * HH + tid], wd = w1[(i + 3) * HH + tid];
#pragma unroll
        for (int t = 0; t < T; t++) {
            float4 v = *reinterpret_cast<const float4*>(&sM[t * NF + i]);
            acc[t] = fmaf(v.x, wa, acc[t]); acc[t] = fmaf(v.y, wb, acc[t]);
            acc[t] = fmaf(v.z, wc, acc[t]); acc[t] = fmaf(v.w, wd, acc[t]);
        }
    }
#pragma unroll
    for (int t = 0; t < T; t++) sH[t * HH + tid] = fmaxf(acc[t], 0.f);
    __syncthreads();

    for (int o = tid; o < T * NF; o += 128) {
        int t = o >> 4, c = o & 15;
        float v = b2[c];
#pragma unroll 1
        for (int k = 0; k < HH; k += 4) {
            float4 h = *reinterpret_cast<const float4*>(&sH[t * HH + k]);
            v = fmaf(h.x, w2[(k + 0) * NF + c], v);
            v = fmaf(h.y, w2[(k + 1) * NF + c], v);
            v = fmaf(h.z, w2[(k + 2) * NF + c], v);
            v = fmaf(h.w, w2[(k + 3) * NF + c], v);
        }
        g_h0[n0 * NF + o] = v + x[n0 * NF + o];
    }
}

// ---------------- GEMM: out[M,128] = op(in[M,K] @ W[K,128])  T=32 rows/block ----
template <int K, int BIASMODE, bool RELU>
__global__ void __launch_bounds__(128) k_mm(
    int insel, const float* __restrict__ in_ext,
    float* __restrict__ outp,
    const float* __restrict__ W, const float* __restrict__ bias)
{
    constexpr int T = 32;
    __shared__ __align__(16) float sIn[T * K];
    const float* in = sel_in(insel, in_ext);
    int tid = threadIdx.x;
    int j = tid;
    int n0 = blockIdx.x * T;

    const float4* gsrc = reinterpret_cast<const float4*>(in + (size_t)n0 * K);
    float4* ssrc = reinterpret_cast<float4*>(sIn);
    for (int o = tid; o < T * K / 4; o += 128) ssrc[o] = gsrc[o];
    __syncthreads();

    float acc[T];
    if (BIASMODE == 1) {
        float b = bias[j];
#pragma unroll
        for (int t = 0; t < T; t++) acc[t] = b;
    } else {
#pragma unroll
        for (int t = 0; t < T; t++) acc[t] = 0.f;
    }

#pragma unroll 1
    for (int k = 0; k < K; k += 4) {
        float wa = W[(k + 0) * HH + j], wb = W[(k + 1) * HH + j];
        float wc = W[(k + 2) * HH + j], wd = W[(k + 3) * HH + j];
#pragma unroll
        for (int t = 0; t < T; t++) {
            float4 v = *reinterpret_cast<const float4*>(&sIn[t * K + k]);
            acc[t] = fmaf(v.x, wa, acc[t]); acc[t] = fmaf(v.y, wb, acc[t]);
            acc[t] = fmaf(v.z, wc, acc[t]); acc[t] = fmaf(v.w, wd, acc[t]);
        }
    }

#pragma unroll
    for (int t = 0; t < T; t++) {
        float v = acc[t];
        if (RELU) v = fmaxf(v, 0.f);
        outp[(size_t)(n0 + t) * HH + j] = v;
    }
}

// ---------------- twin GEMM via gridDim.y: y=0 -> nb0 (WA,+biasA); y=1 -> nb1 (WB) ----
template <int K>
__global__ void __launch_bounds__(128) k_mm2(
    int insel, const float* __restrict__ in_ext,
    const float* __restrict__ WA, const float* __restrict__ biasA,
    const float* __restrict__ WB)
{
    constexpr int T = 32;
    __shared__ __align__(16) float sIn[T * K];
    const float* in = sel_in(insel, in_ext);
    int tid = threadIdx.x;
    int j = tid;
    int n0 = blockIdx.x * T;
    bool isA = (blockIdx.y == 0);
    const float* W = isA ? WA : WB;
    float* outp = g_nb[isA ? 0 : 1];

    const float4* gsrc = reinterpret_cast<const float4*>(in + (size_t)n0 * K);
    float4* ssrc = reinterpret_cast<float4*>(sIn);
    for (int o = tid; o < T * K / 4; o += 128) ssrc[o] = gsrc[o];
    __syncthreads();

    float acc[T];
    float b = isA ? biasA[j] : 0.f;
#pragma unroll
    for (int t = 0; t < T; t++) acc[t] = b;

#pragma unroll 1
    for (int k = 0; k < K; k += 4) {
        float wa = W[(k + 0) * HH + j], wb = W[(k + 1) * HH + j];
        float wc = W[(k + 2) * HH + j], wd = W[(k + 3) * HH + j];
#pragma unroll
        for (int t = 0; t < T; t++) {
            float4 v = *reinterpret_cast<const float4*>(&sIn[t * K + k]);
            acc[t] = fmaf(v.x, wa, acc[t]); acc[t] = fmaf(v.y, wb, acc[t]);
            acc[t] = fmaf(v.z, wc, acc[t]); acc[t] = fmaf(v.w, wd, acc[t]);
        }
    }
#pragma unroll
    for (int t = 0; t < T; t++)
        outp[(size_t)(n0 + t) * HH + j] = acc[t];
}

// ---------------- TAG tail GEMM: nb4 = relu(nb4 + [h1|h2|h3] @ tagw[1..3]) ----
// nb4 already holds bias + lin0(h0) (computed on a side stream during the hops).
__global__ void __launch_bounds__(128) k_mmTAG384(
    const float* __restrict__ tagw1)
{
    constexpr int T = 16, K = 384;
    __shared__ __align__(16) float sIn[T * K];   // 24 KB
    int tid = threadIdx.x;
    int j = tid;
    int n0 = blockIdx.x * T;

    for (int o = tid; o < T * K / 4; o += 128) {
        int f = o * 4;
        int t = f / K;
        int rem = f - t * K;
        int seg = rem >> 7;
        int c = rem & 127;
        const float* b = g_nb[seg];   // h1=nb0, h2=nb1, h3=nb2
        reinterpret_cast<float4*>(sIn)[o] =
            *reinterpret_cast<const float4*>(&b[(size_t)(n0 + t) * HH + c]);
    }
    __syncthreads();

    float acc[T];
#pragma unroll
    for (int t = 0; t < T; t++) acc[t] = g_nb[4][(size_t)(n0 + t) * HH + j];

#pragma unroll 1
    for (int k = 0; k < K; k += 4) {
        float wa = tagw1[(k + 0) * HH + j], wb = tagw1[(k + 1) * HH + j];
        float wc = tagw1[(k + 2) * HH + j], wd = tagw1[(k + 3) * HH + j];
#pragma unroll
        for (int t = 0; t < T; t++) {
            float4 v = *reinterpret_cast<const float4*>(&sIn[t * K + k]);
            acc[t] = fmaf(v.x, wa, acc[t]); acc[t] = fmaf(v.y, wb, acc[t]);
            acc[t] = fmaf(v.z, wc, acc[t]); acc[t] = fmaf(v.w, wd, acc[t]);
        }
    }
#pragma unroll
    for (int t = 0; t < T; t++)
        g_nb[4][(size_t)(n0 + t) * HH + j] = fmaxf(acc[t], 0.f);
}

// ---------------- fused agg + layer-2 GEMM ----------------
// Phase 1 (8 warps, 4 nodes each): S[n] = sum_e relu(A[n] + B[src] + C[ea]) -> smem
// Phase 2: out[n0..n0+31] = op(S @ W2 + deg*b2)   (RELU selectable)
template <bool RELU>
__global__ void __launch_bounds__(256) k_agg_mm(
    int msel, float* __restrict__ outp,
    const float* __restrict__ W, const float* __restrict__ bias)
{
    constexpr int T = 32;
    __shared__ __align__(16) float sS[T * HH];   // 16 KB
    const float4* __restrict__ A = reinterpret_cast<const float4*>(g_nb[0]);
    const float4* __restrict__ B = reinterpret_cast<const float4*>(g_nb[1]);
    const float4* __restrict__ M = reinterpret_cast<const float4*>(g_msg[msel]);
    int tid = threadIdx.x;
    int lane = tid & 31, wid = tid >> 5;
    int n0 = blockIdx.x * T;

    // phase 1: gather-aggregate 4 nodes per warp
    for (int u = 0; u < 4; u++) {
        int r = wid * 4 + u;
        int n = n0 + r;
        int beg = g_rowoff[n], len = g_deg[n];
        float4 a = A[(size_t)n * 32 + lane];
        float4 acc = make_float4(0.f, 0.f, 0.f, 0.f);
        for (int i = 0; i < len; i++) {
            int s  = __ldg(&g_csr_src[beg + i]);
            int ea = __ldg(&g_csr_ea[beg + i]);
            float4 b = __ldg(&B[(size_t)s * 32 + lane]);
            float4 m = __ldg(&M[(size_t)ea * 32 + lane]);
            acc.x += fmaxf(a.x + b.x + m.x, 0.f);
            acc.y += fmaxf(a.y + b.y + m.y, 0.f);
            acc.z += fmaxf(a.z + b.z + m.z, 0.f);
            acc.w += fmaxf(a.w + b.w + m.w, 0.f);
        }
        *reinterpret_cast<float4*>(&sS[r * HH + lane * 4]) = acc;
    }
    __syncthreads();

    // phase 2: GEMM, 2 groups of 128 threads, 16 rows each
    int j = tid & 127;
    int g = tid >> 7;
    int tbase = g * 16;
    float acc[16];
    float bj = bias[j];
#pragma unroll
    for (int t = 0; t < 16; t++) acc[t] = bj * (float)g_deg[n0 + tbase + t];

#pragma unroll 1
    for (int k = 0; k < HH; k += 4) {
        float wa = W[(k + 0) * HH + j], wb = W[(k + 1) * HH + j];
        float wc = W[(k + 2) * HH + j], wd = W[(k + 3) * HH + j];
#pragma unroll
        for (int t = 0; t < 16; t++) {
            float4 v = *reinterpret_cast<const float4*>(&sS[(tbase + t) * HH + k]);
            acc[t] = fmaf(v.x, wa, acc[t]); acc[t] = fmaf(v.y, wb, acc[t]);
            acc[t] = fmaf(v.z, wc, acc[t]); acc[t] = fmaf(v.w, wd, acc[t]);
        }
    }
#pragma unroll
    for (int t = 0; t < 16; t++) {
        float v = acc[t];
        if (RELU) v = fmaxf(v, 0.f);
        outp[(size_t)(n0 + tbase + t) * HH + j] = v;
    }
}

// ---------------- fused agg + final 16-col GEMM -> d_out ----------------
__global__ void __launch_bounds__(256) k_agg_out16(
    int msel, float* __restrict__ out,
    const float* __restrict__ W2, const float* __restrict__ b2)
{
    constexpr int T = 32;
    __shared__ __align__(16) float sS[T * HH];
    const float4* __restrict__ A = reinterpret_cast<const float4*>(g_nb[0]);
    const float4* __restrict__ B = reinterpret_cast<const float4*>(g_nb[1]);
    const float4* __restrict__ M = reinterpret_cast<const float4*>(g_msg[msel]);
    int tid = threadIdx.x;
    int lane = tid & 31, wid = tid >> 5;
    int n0 = blockIdx.x * T;

    for (int u = 0; u < 4; u++) {
        int r = wid * 4 + u;
        int n = n0 + r;
        int beg = g_rowoff[n], len = g_deg[n];
        float4 a = A[(size_t)n * 32 + lane];
        float4 acc = make_float4(0.f, 0.f, 0.f, 0.f);
        for (int i = 0; i < len; i++) {
            int s  = __ldg(&g_csr_src[beg + i]);
            int ea = __ldg(&g_csr_ea[beg + i]);
            float4 b = __ldg(&B[(size_t)s * 32 + lane]);
            float4 m = __ldg(&M[(size_t)ea * 32 + lane]);
            acc.x += fmaxf(a.x + b.x + m.x, 0.f);
            acc.y += fmaxf(a.y + b.y + m.y, 0.f);
            acc.z += fmaxf(a.z + b.z + m.z, 0.f);
            acc.w += fmaxf(a.w + b.w + m.w, 0.f);
        }
        *reinterpret_cast<float4*>(&sS[r * HH + lane * 4]) = acc;
    }
    __syncthreads();

    // phase 2: 32 rows x 16 cols = 512 outputs, 2 per thread
    int row = tid >> 3;
    int c0 = (tid & 7) * 2;
    int n = n0 + row;
    float dg = (float)g_deg[n];
    float a0 = b2[c0] * dg, a1 = b2[c0 + 1] * dg;
#pragma unroll 4
    for (int k = 0; k < HH; k++) {
        float s = sS[row * HH + k];
        a0 = fmaf(s, __ldg(&W2[k * 16 + c0]), a0);
        a1 = fmaf(s, __ldg(&W2[k * 16 + c0 + 1]), a1);
    }
    out[n * 16 + c0] = a0;
    out[n * 16 + c0 + 1] = a1;
}

// ---------------- TAG hop (warp per node, float4 lanes) ----------------
__global__ void __launch_bounds__(256) k_hop(int insel, int outsel) {
    const float4* __restrict__ hin = reinterpret_cast<const float4*>(g_nb[insel]);
    float4* __restrict__ hout = reinterpret_cast<float4*>(g_nb[outsel]);
    int lane = threadIdx.x & 31;
    int n = blockIdx.x * 8 + (threadIdx.x >> 5);
    if (n >= NNODE) return;
    int beg = g_rowoff[n], len = g_deg[n];
    float4 acc = make_float4(0.f, 0.f, 0.f, 0.f);
    for (int i = 0; i < len; i++) {
        int s = __ldg(&g_csr_src[beg + i]);
        float d = __ldg(&g_dis[s]);
        float4 h = __ldg(&hin[(size_t)s * 32 + lane]);
        acc.x = fmaf(d, h.x, acc.x);
        acc.y = fmaf(d, h.y, acc.y);
        acc.z = fmaf(d, h.z, acc.z);
        acc.w = fmaf(d, h.w, acc.w);
    }
    float dn = g_dis[n];
    acc.x *= dn; acc.y *= dn; acc.z *= dn; acc.w *= dn;
    hout[(size_t)n * 32 + lane] = acc;
}

// ---------------- launch ----------------
extern "C" void kernel_launch(void* const* d_in, const int* in_sizes, int n_in,
                              void* d_out, int out_size)
{
    static const int ESZ[24] = {
        320000, 320000, 2560000, 320000,
        2048, 128, 2048, 16,
        6144, 128, 16384, 128,
        65536, 128,
        34816, 128, 16384, 128,
        65536, 128,
        34816, 128, 2048, 16};
    static const int M_DICT[24] = {0,1,2,3,4,5,6,7,8,9,10,11,12,13,14,15,16,17,18,19,20,21,22,23};
    static const int M_SIG[24]  = {0,1,2,23,3,4,5,6,7,8,9,10,11,12,13,14,15,16,17,18,19,20,21,22};
    static const int M_ALPHA[24]= {23,18,12,13,16,14,17,15,2,0,3,1,20,19,6,4,7,5,22,21,10,8,11,9};
    const int* cands[3] = {M_DICT, M_SIG, M_ALPHA};
    const int* map = M_DICT;
    for (int ci = 0; ci < 3; ci++) {
        bool ok = (n_in >= 24);
        for (int l = 0; l < 24 && ok; l++) ok = (in_sizes[cands[ci][l]] == ESZ[l]);
        if (ok) { map = cands[ci]; break; }
    }
#define INP(l) ((const float*)d_in[map[l]])
    const float* x     = INP(0);
    const float* mask  = INP(1);
    const float* eattr = INP(2);
    const int*   ei    = (const int*)d_in[map[3]];
    const float *m_w1 = INP(4), *m_b1 = INP(5), *m_w2 = INP(6), *m_b2 = INP(7);
    const float *ea0w1 = INP(8), *ea0b1 = INP(9), *ea0w2 = INP(10), *ea0b2 = INP(11);
    const float *tag0w = INP(12), *tag0b = INP(13);
    const float *ea1w1 = INP(14), *ea1b1 = INP(15), *ea1w2 = INP(16), *ea1b2 = INP(17);
    const float *tag1w = INP(18), *tag1b = INP(19);
    const float *ea2w1 = INP(20), *ea2b1 = INP(21), *ea2w2 = INP(22), *ea2b2 = INP(23);
#undef INP
    float* out = (float*)d_out;
    (void)out_size;

    const int GN32 = NNODE / 32;   // 625
    const int GN16 = NNODE / 16;   // 1250
    const int GE32 = NEDGE / 32;   // 5000
    const int GW   = NNODE / 8;    // 2500

    static float* s_nb[5] = {nullptr, nullptr, nullptr, nullptr, nullptr};
    static float* s_msg[3] = {nullptr, nullptr, nullptr};
    static cudaStream_t s1 = nullptr, s2 = nullptr;
    static cudaEvent_t evFork = nullptr, evS1 = nullptr, evS2 = nullptr;
    static cudaEvent_t evT0 = nullptr, evC1 = nullptr, evL0 = nullptr;
    static cudaEvent_t evT1 = nullptr, evC2 = nullptr, evL1 = nullptr;
    if (!s_nb[0]) {
        void* p = nullptr;
        cudaGetSymbolAddress(&p, g_nb);
        for (int i = 0; i < 5; i++) s_nb[i] = (float*)p + (size_t)i * NNODE * HH;
        cudaGetSymbolAddress(&p, g_msg);
        for (int i = 0; i < 3; i++) s_msg[i] = (float*)p + (size_t)i * NEDGE * HH;
        cudaStreamCreateWithFlags(&s1, cudaStreamNonBlocking);
        cudaStreamCreateWithFlags(&s2, cudaStreamNonBlocking);
        cudaEventCreateWithFlags(&evFork, cudaEventDisableTiming);
        cudaEventCreateWithFlags(&evS1, cudaEventDisableTiming);
        cudaEventCreateWithFlags(&evS2, cudaEventDisableTiming);
        cudaEventCreateWithFlags(&evT0, cudaEventDisableTiming);
        cudaEventCreateWithFlags(&evC1, cudaEventDisableTiming);
        cudaEventCreateWithFlags(&evL0, cudaEventDisableTiming);
        cudaEventCreateWithFlags(&evT1, cudaEventDisableTiming);
        cudaEventCreateWithFlags(&evC2, cudaEventDisableTiming);
        cudaEventCreateWithFlags(&evL1, cudaEventDisableTiming);
    }

    // ---- fork: CSR build on main; node GEMMs on s1; layer-0 C GEMM on s2 ----
    cudaEventRecord(evFork, 0);
    cudaStreamWaitEvent(s1, evFork, 0);
    cudaStreamWaitEvent(s2, evFork, 0);

    k_zero<<<(NNODE + 255) / 256, 256>>>();
    k_hist<<<E2 / 256, 256>>>(ei);
    k_scan<<<1, 1024>>>();
    k_scatter<<<E2 / 256, 256>>>(ei);

    k_maskmlp<<<GN16, 128, 0, s1>>>(x, mask, m_w1, m_b1, m_w2, m_b2);
    k_mm2<16><<<dim3(GN32, 2), 128, 0, s1>>>(-3, nullptr, ea0w1, ea0b1, ea0w1 + 16 * HH);

    k_mm<16, 0, false><<<GE32, 128, 0, s2>>>(-1, eattr, s_msg[0], ea0w1 + 32 * HH, nullptr);

    cudaEventRecord(evS1, s1);
    cudaEventRecord(evS2, s2);
    cudaStreamWaitEvent(0, evS1, 0);
    cudaStreamWaitEvent(0, evS2, 0);

    // ---- EA0: fused agg + layer-2 -> nb3 ----
    k_agg_mm<true><<<GN32, 256>>>(0, s_nb[3], ea0w2, ea0b2);

    // ---- TAG0: lin0 on s1, C1 on s2, hops on main, then K=384 tail ----
    cudaEventRecord(evT0, 0);
    cudaStreamWaitEvent(s1, evT0, 0);
    cudaStreamWaitEvent(s2, evT0, 0);
    k_mm<128, 1, false><<<GN32, 128, 0, s1>>>(3, nullptr, s_nb[4], tag0w, tag0b);
    cudaEventRecord(evL0, s1);
    k_mm<16, 0, false><<<GE32, 128, 0, s2>>>(-1, eattr, s_msg[1], ea1w1 + 256 * HH, nullptr);
    cudaEventRecord(evC1, s2);

    k_hop<<<GW, 256>>>(3, 0);
    k_hop<<<GW, 256>>>(0, 1);
    k_hop<<<GW, 256>>>(1, 2);
    cudaStreamWaitEvent(0, evL0, 0);
    k_mmTAG384<<<GN16, 128>>>(tag0w + HH * HH);

    // ---- EA1 (nb4 -> 128) -> nb3 ----
    k_mm2<128><<<dim3(GN32, 2), 128>>>(4, nullptr, ea1w1, ea1b1, ea1w1 + 128 * HH);
    cudaStreamWaitEvent(0, evC1, 0);
    k_agg_mm<true><<<GN32, 256>>>(1, s_nb[3], ea1w2, ea1b2);

    // ---- TAG1: lin0 on s1, C2 on s2, hops on main, K=384 tail ----
    cudaEventRecord(evT1, 0);
    cudaStreamWaitEvent(s1, evT1, 0);
    cudaStreamWaitEvent(s2, evT1, 0);
    k_mm<128, 1, false><<<GN32, 128, 0, s1>>>(3, nullptr, s_nb[4], tag1w, tag1b);
    cudaEventRecord(evL1, s1);
    k_mm<16, 0, false><<<GE32, 128, 0, s2>>>(-1, eattr, s_msg[2], ea2w1 + 256 * HH, nullptr);
    cudaEventRecord(evC2, s2);

    k_hop<<<GW, 256>>>(3, 0);
    k_hop<<<GW, 256>>>(0, 1);
    k_hop<<<GW, 256>>>(1, 2);
    cudaStreamWaitEvent(0, evL1, 0);
    k_mmTAG384<<<GN16, 128>>>(tag1w + HH * HH);

    // ---- EA2 (nb4 -> 16) -> d_out ----
    k_mm2<128><<<dim3(GN32, 2), 128>>>(4, nullptr, ea2w1, ea2b1, ea2w1 + 128 * HH);
    cudaStreamWaitEvent(0, evC2, 0);
    k_agg_out16<<<GN32, 256>>>(2, out, ea2w2, ea2b2);
}

// round 13
// speedup vs baseline: 1.3577x; 1.0057x over previous
#include <cuda_runtime.h>
#include <math.h>

#define NNODE 20000
#define NEDGE 160000
#define E2    320000
#define HH    128
#define NF    16
#define EF    16

// ---------------- device scratch (no allocations allowed) ----------------
__device__ int   g_deg[NNODE];
__device__ int   g_rowoff[NNODE];
__device__ int   g_cursor[NNODE];
__device__ float g_dis[NNODE];
__device__ int   g_csr_src[E2];
__device__ int   g_csr_ea[E2];                 // eattr index (0..NEDGE)
__device__ float g_h0[NNODE * NF];
__device__ float g_nb[5][NNODE * HH];          // node-feature buffers
__device__ float g_msg[3][(size_t)NEDGE * HH]; // per-unique-edge C buffers

__device__ __forceinline__ const float* sel_in(int s, const float* ext) {
    if (s >= 0) return g_nb[s];
    if (s == -3) return g_h0;
    return ext;
}

// ---------------- graph structure build ----------------
__global__ void k_zero() {
    int i = blockIdx.x * 256 + threadIdx.x;
    if (i < NNODE) g_deg[i] = 0;
}

__global__ void k_hist(const int* __restrict__ ei) {
    int e = blockIdx.x * 256 + threadIdx.x;
    if (e >= E2) return;
    int d = (e < NEDGE) ? ei[NEDGE + e] : ei[e - NEDGE];
    atomicAdd(&g_deg[d], 1);
}

// warp-shuffle block scan (single block, 1024 threads, 20 elems/thread)
__global__ void k_scan() {
    __shared__ int wsum[32];
    int t = threadIdx.x, lane = t & 31, wid = t >> 5;
    const int PER = 20;
    int base = t * PER;
    int s = 0;
#pragma unroll
    for (int i = 0; i < PER; i++) { int idx = base + i; if (idx < NNODE) s += g_deg[idx]; }
    int x = s;
#pragma unroll
    for (int off = 1; off < 32; off <<= 1) {
        int y = __shfl_up_sync(0xffffffffu, x, off);
        if (lane >= off) x += y;
    }
    if (lane == 31) wsum[wid] = x;
    __syncthreads();
    if (wid == 0) {
        int y = wsum[lane];
#pragma unroll
        for (int off = 1; off < 32; off <<= 1) {
            int z = __shfl_up_sync(0xffffffffu, y, off);
            if (lane >= off) y += z;
        }
        wsum[lane] = y;
    }
    __syncthreads();
    int run = x - s + (wid > 0 ? wsum[wid - 1] : 0);
#pragma unroll
    for (int i = 0; i < PER; i++) {
        int idx = base + i;
        if (idx < NNODE) {
            int v = g_deg[idx];
            g_rowoff[idx] = run;
            g_cursor[idx] = run;
            g_dis[idx] = (v > 0) ? rsqrtf((float)v) : 0.f;
            run += v;
        }
    }
}

__global__ void k_scatter(const int* __restrict__ ei) {
    int e = blockIdx.x * 256 + threadIdx.x;
    if (e >= E2) return;
    int srcv = ei[e];
    int d  = (e < NEDGE) ? ei[NEDGE + e] : ei[e - NEDGE];
    int ea = (e < NEDGE) ? e : e - NEDGE;
    int slot = atomicAdd(&g_cursor[d], 1);
    g_csr_src[slot] = srcv;
    g_csr_ea[slot]  = ea;
}

// ---------------- mask MLP + residual: g_h0 = mlp2(mask) + x ----------------
__global__ void __launch_bounds__(128) k_maskmlp(
    const float* __restrict__ x, const float* __restrict__ mask,
    const float* __restrict__ w1, const float* __restrict__ b1,
    const float* __restrict__ w2, const float* __restrict__ b2)
{
    constexpr int T = 16;
    __shared__ __align__(16) float sM[T * NF];
    __shared__ __align__(16) float sH[T * HH];
    int tid = threadIdx.x;
    int n0 = blockIdx.x * T;
    for (int o = tid; o < T * NF; o += 128) sM[o] = mask[n0 * NF + o];
    __syncthreads();

    float acc[T];
    float bj = b1[tid];
#pragma unroll
    for (int t = 0; t < T; t++) acc[t] = bj;
#pragma unroll
    for (int i = 0; i < NF; i += 4) {
        float wa = w1[(i + 0) * HH + tid], wb = w1[(i + 1) * HH + tid];
        float wc = w1[(i + 2) * HH + tid], wd = w1[(i + 3) * HH + tid];
#pragma unroll
        for (int t = 0; t < T; t++) {
            float4 v = *reinterpret_cast<const float4*>(&sM[t * NF + i]);
            acc[t] = fmaf(v.x, wa, acc[t]); acc[t] = fmaf(v.y, wb, acc[t]);
            acc[t] = fmaf(v.z, wc, acc[t]); acc[t] = fmaf(v.w, wd, acc[t]);
        }
    }
#pragma unroll
    for (int t = 0; t < T; t++) sH[t * HH + tid] = fmaxf(acc[t], 0.f);
    __syncthreads();

    for (int o = tid; o < T * NF; o += 128) {
        int t = o >> 4, c = o & 15;
        float v = b2[c];
#pragma unroll 1
        for (int k = 0; k < HH; k += 4) {
            float4 h = *reinterpret_cast<const float4*>(&sH[t * HH + k]);
            v = fmaf(h.x, w2[(k + 0) * NF + c], v);
            v = fmaf(h.y, w2[(k + 1) * NF + c], v);
            v = fmaf(h.z, w2[(k + 2) * NF + c], v);
            v = fmaf(h.w, w2[(k + 3) * NF + c], v);
        }
        g_h0[n0 * NF + o] = v + x[n0 * NF + o];
    }
}

// ---------------- GEMM: out[M,128] = op(in[M,K] @ W[K,128])  T=32 rows/block ----
template <int K, int BIASMODE, bool RELU>
__global__ void __launch_bounds__(128) k_mm(
    int insel, const float* __restrict__ in_ext,
    float* __restrict__ outp,
    const float* __restrict__ W, const float* __restrict__ bias)
{
    constexpr int T = 32;
    __shared__ __align__(16) float sIn[T * K];
    const float* in = sel_in(insel, in_ext);
    int tid = threadIdx.x;
    int j = tid;
    int n0 = blockIdx.x * T;

    const float4* gsrc = reinterpret_cast<const float4*>(in + (size_t)n0 * K);
    float4* ssrc = reinterpret_cast<float4*>(sIn);
    for (int o = tid; o < T * K / 4; o += 128) ssrc[o] = gsrc[o];
    __syncthreads();

    float acc[T];
    if (BIASMODE == 1) {
        float b = bias[j];
#pragma unroll
        for (int t = 0; t < T; t++) acc[t] = b;
    } else {
#pragma unroll
        for (int t = 0; t < T; t++) acc[t] = 0.f;
    }

#pragma unroll 1
    for (int k = 0; k < K; k += 4) {
        float wa = W[(k + 0) * HH + j], wb = W[(k + 1) * HH + j];
        float wc = W[(k + 2) * HH + j], wd = W[(k + 3) * HH + j];
#pragma unroll
        for (int t = 0; t < T; t++) {
            float4 v = *reinterpret_cast<const float4*>(&sIn[t * K + k]);
            acc[t] = fmaf(v.x, wa, acc[t]); acc[t] = fmaf(v.y, wb, acc[t]);
            acc[t] = fmaf(v.z, wc, acc[t]); acc[t] = fmaf(v.w, wd, acc[t]);
        }
    }

#pragma unroll
    for (int t = 0; t < T; t++) {
        float v = acc[t];
        if (RELU) v = fmaxf(v, 0.f);
        outp[(size_t)(n0 + t) * HH + j] = v;
    }
}

// ---------------- twin GEMM via gridDim.y: y=0 -> nb0 (WA,+biasA); y=1 -> nb1 (WB) ----
template <int K>
__global__ void __launch_bounds__(128) k_mm2(
    int insel, const float* __restrict__ in_ext,
    const float* __restrict__ WA, const float* __restrict__ biasA,
    const float* __restrict__ WB)
{
    constexpr int T = 32;
    __shared__ __align__(16) float sIn[T * K];
    const float* in = sel_in(insel, in_ext);
    int tid = threadIdx.x;
    int j = tid;
    int n0 = blockIdx.x * T;
    bool isA = (blockIdx.y == 0);
    const float* W = isA ? WA : WB;
    float* outp = g_nb[isA ? 0 : 1];

    const float4* gsrc = reinterpret_cast<const float4*>(in + (size_t)n0 * K);
    float4* ssrc = reinterpret_cast<float4*>(sIn);
    for (int o = tid; o < T * K / 4; o += 128) ssrc[o] = gsrc[o];
    __syncthreads();

    float acc[T];
    float b = isA ? biasA[j] : 0.f;
#pragma unroll
    for (int t = 0; t < T; t++) acc[t] = b;

#pragma unroll 1
    for (int k = 0; k < K; k += 4) {
        float wa = W[(k + 0) * HH + j], wb = W[(k + 1) * HH + j];
        float wc = W[(k + 2) * HH + j], wd = W[(k + 3) * HH + j];
#pragma unroll
        for (int t = 0; t < T; t++) {
            float4 v = *reinterpret_cast<const float4*>(&sIn[t * K + k]);
            acc[t] = fmaf(v.x, wa, acc[t]); acc[t] = fmaf(v.y, wb, acc[t]);
            acc[t] = fmaf(v.z, wc, acc[t]); acc[t] = fmaf(v.w, wd, acc[t]);
        }
    }
#pragma unroll
    for (int t = 0; t < T; t++)
        outp[(size_t)(n0 + t) * HH + j] = acc[t];
}

// ---------------- fused TAG hop + lin GEMM ----------------
// Phase 1: h_new[n] = dis[n] * sum dis[s] * h_prev[s]  -> smem tile (+ optional global)
//          (NSEG==2 additionally stages h_prev rows n0.. directly as K-segment 0)
// Phase 2: nb4 op= [segments] @ W   with W = NSEG*128 contiguous rows of tagw.
// ACCMODE: 0 = init with bias, 1 = accumulate, 2 = accumulate + relu.
template <int NSEG, int ACCMODE>
__global__ void __launch_bounds__(256) k_hop_mm(
    int insel, int outsel,
    const float* __restrict__ W, const float* __restrict__ bias)
{
    constexpr int T = 32;
    constexpr int K = NSEG * 128;
    __shared__ __align__(16) float sIn[T * K];
    const float4* __restrict__ hin4 = reinterpret_cast<const float4*>(g_nb[insel]);
    int tid = threadIdx.x, lane = tid & 31, wid = tid >> 5;
    int n0 = blockIdx.x * T;

    // stage h_prev rows as segment 0 (NSEG==2 only)
    if (NSEG == 2) {
        const float4* src = hin4 + (size_t)n0 * 32;
        for (int o = tid; o < T * 32; o += 256) {
            int r = o >> 5, c = o & 31;
            *reinterpret_cast<float4*>(&sIn[r * K + c * 4]) = src[(size_t)r * 32 + c];
        }
    }

    // hop gather: 8 warps x 4 nodes -> segment NSEG-1
    const int cbase = (NSEG - 1) * 128;
    float4* houtg = (outsel >= 0) ? reinterpret_cast<float4*>(g_nb[outsel]) : nullptr;
    for (int u = 0; u < 4; u++) {
        int r = wid * 4 + u;
        int n = n0 + r;
        int beg = g_rowoff[n], len = g_deg[n];
        float4 acc = make_float4(0.f, 0.f, 0.f, 0.f);
        for (int i = 0; i < len; i++) {
            int s = __ldg(&g_csr_src[beg + i]);
            float d = __ldg(&g_dis[s]);
            float4 h = __ldg(&hin4[(size_t)s * 32 + lane]);
            acc.x = fmaf(d, h.x, acc.x);
            acc.y = fmaf(d, h.y, acc.y);
            acc.z = fmaf(d, h.z, acc.z);
            acc.w = fmaf(d, h.w, acc.w);
        }
        float dn = g_dis[n];
        acc.x *= dn; acc.y *= dn; acc.z *= dn; acc.w *= dn;
        *reinterpret_cast<float4*>(&sIn[r * K + cbase + lane * 4]) = acc;
        if (houtg) houtg[(size_t)n * 32 + lane] = acc;
    }
    __syncthreads();

    // phase 2: GEMM into nb4; 2 groups of 128 threads, 16 rows each
    float* out = g_nb[4];
    int j = tid & 127;
    int g = tid >> 7;
    int tb = g * 16;
    float acc[16];
    if (ACCMODE == 0) {
        float b = bias[j];
#pragma unroll
        for (int t = 0; t < 16; t++) acc[t] = b;
    } else {
#pragma unroll
        for (int t = 0; t < 16; t++) acc[t] = out[(size_t)(n0 + tb + t) * HH + j];
    }

#pragma unroll 1
    for (int k = 0; k < K; k += 4) {
        float wa = W[(k + 0) * HH + j], wb = W[(k + 1) * HH + j];
        float wc = W[(k + 2) * HH + j], wd = W[(k + 3) * HH + j];
#pragma unroll
        for (int t = 0; t < 16; t++) {
            float4 v = *reinterpret_cast<const float4*>(&sIn[(tb + t) * K + k]);
            acc[t] = fmaf(v.x, wa, acc[t]); acc[t] = fmaf(v.y, wb, acc[t]);
            acc[t] = fmaf(v.z, wc, acc[t]); acc[t] = fmaf(v.w, wd, acc[t]);
        }
    }
#pragma unroll
    for (int t = 0; t < 16; t++) {
        float v = acc[t];
        if (ACCMODE == 2) v = fmaxf(v, 0.f);
        out[(size_t)(n0 + tb + t) * HH + j] = v;
    }
}

// ---------------- fused agg + layer-2 GEMM ----------------
template <bool RELU>
__global__ void __launch_bounds__(256) k_agg_mm(
    int msel, float* __restrict__ outp,
    const float* __restrict__ W, const float* __restrict__ bias)
{
    constexpr int T = 32;
    __shared__ __align__(16) float sS[T * HH];   // 16 KB
    const float4* __restrict__ A = reinterpret_cast<const float4*>(g_nb[0]);
    const float4* __restrict__ B = reinterpret_cast<const float4*>(g_nb[1]);
    const float4* __restrict__ M = reinterpret_cast<const float4*>(g_msg[msel]);
    int tid = threadIdx.x;
    int lane = tid & 31, wid = tid >> 5;
    int n0 = blockIdx.x * T;

    for (int u = 0; u < 4; u++) {
        int r = wid * 4 + u;
        int n = n0 + r;
        int beg = g_rowoff[n], len = g_deg[n];
        float4 a = A[(size_t)n * 32 + lane];
        float4 acc = make_float4(0.f, 0.f, 0.f, 0.f);
        for (int i = 0; i < len; i++) {
            int s  = __ldg(&g_csr_src[beg + i]);
            int ea = __ldg(&g_csr_ea[beg + i]);
            float4 b = __ldg(&B[(size_t)s * 32 + lane]);
            float4 m = __ldg(&M[(size_t)ea * 32 + lane]);
            acc.x += fmaxf(a.x + b.x + m.x, 0.f);
            acc.y += fmaxf(a.y + b.y + m.y, 0.f);
            acc.z += fmaxf(a.z + b.z + m.z, 0.f);
            acc.w += fmaxf(a.w + b.w + m.w, 0.f);
        }
        *reinterpret_cast<float4*>(&sS[r * HH + lane * 4]) = acc;
    }
    __syncthreads();

    int j = tid & 127;
    int g = tid >> 7;
    int tbase = g * 16;
    float acc[16];
    float bj = bias[j];
#pragma unroll
    for (int t = 0; t < 16; t++) acc[t] = bj * (float)g_deg[n0 + tbase + t];

#pragma unroll 1
    for (int k = 0; k < HH; k += 4) {
        float wa = W[(k + 0) * HH + j], wb = W[(k + 1) * HH + j];
        float wc = W[(k + 2) * HH + j], wd = W[(k + 3) * HH + j];
#pragma unroll
        for (int t = 0; t < 16; t++) {
            float4 v = *reinterpret_cast<const float4*>(&sS[(tbase + t) * HH + k]);
            acc[t] = fmaf(v.x, wa, acc[t]); acc[t] = fmaf(v.y, wb, acc[t]);
            acc[t] = fmaf(v.z, wc, acc[t]); acc[t] = fmaf(v.w, wd, acc[t]);
        }
    }
#pragma unroll
    for (int t = 0; t < 16; t++) {
        float v = acc[t];
        if (RELU) v = fmaxf(v, 0.f);
        outp[(size_t)(n0 + tbase + t) * HH + j] = v;
    }
}

// ---------------- fused agg + final 16-col GEMM -> d_out ----------------
__global__ void __launch_bounds__(256) k_agg_out16(
    int msel, float* __restrict__ out,
    const float* __restrict__ W2, const float* __restrict__ b2)
{
    constexpr int T = 32;
    __shared__ __align__(16) float sS[T * HH];
    const float4* __restrict__ A = reinterpret_cast<const float4*>(g_nb[0]);
    const float4* __restrict__ B = reinterpret_cast<const float4*>(g_nb[1]);
    const float4* __restrict__ M = reinterpret_cast<const float4*>(g_msg[msel]);
    int tid = threadIdx.x;
    int lane = tid & 31, wid = tid >> 5;
    int n0 = blockIdx.x * T;

    for (int u = 0; u < 4; u++) {
        int r = wid * 4 + u;
        int n = n0 + r;
        int beg = g_rowoff[n], len = g_deg[n];
        float4 a = A[(size_t)n * 32 + lane];
        float4 acc = make_float4(0.f, 0.f, 0.f, 0.f);
        for (int i = 0; i < len; i++) {
            int s  = __ldg(&g_csr_src[beg + i]);
            int ea = __ldg(&g_csr_ea[beg + i]);
            float4 b = __ldg(&B[(size_t)s * 32 + lane]);
            float4 m = __ldg(&M[(size_t)ea * 32 + lane]);
            acc.x += fmaxf(a.x + b.x + m.x, 0.f);
            acc.y += fmaxf(a.y + b.y + m.y, 0.f);
            acc.z += fmaxf(a.z + b.z + m.z, 0.f);
            acc.w += fmaxf(a.w + b.w + m.w, 0.f);
        }
        *reinterpret_cast<float4*>(&sS[r * HH + lane * 4]) = acc;
    }
    __syncthreads();

    int row = tid >> 3;
    int c0 = (tid & 7) * 2;
    int n = n0 + row;
    float dg = (float)g_deg[n];
    float a0 = b2[c0] * dg, a1 = b2[c0 + 1] * dg;
#pragma unroll 4
    for (int k = 0; k < HH; k++) {
        float s = sS[row * HH + k];
        a0 = fmaf(s, __ldg(&W2[k * 16 + c0]), a0);
        a1 = fmaf(s, __ldg(&W2[k * 16 + c0 + 1]), a1);
    }
    out[n * 16 + c0] = a0;
    out[n * 16 + c0 + 1] = a1;
}

// ---------------- launch ----------------
extern "C" void kernel_launch(void* const* d_in, const int* in_sizes, int n_in,
                              void* d_out, int out_size)
{
    static const int ESZ[24] = {
        320000, 320000, 2560000, 320000,
        2048, 128, 2048, 16,
        6144, 128, 16384, 128,
        65536, 128,
        34816, 128, 16384, 128,
        65536, 128,
        34816, 128, 2048, 16};
    static const int M_DICT[24] = {0,1,2,3,4,5,6,7,8,9,10,11,12,13,14,15,16,17,18,19,20,21,22,23};
    static const int M_SIG[24]  = {0,1,2,23,3,4,5,6,7,8,9,10,11,12,13,14,15,16,17,18,19,20,21,22};
    static const int M_ALPHA[24]= {23,18,12,13,16,14,17,15,2,0,3,1,20,19,6,4,7,5,22,21,10,8,11,9};
    const int* cands[3] = {M_DICT, M_SIG, M_ALPHA};
    const int* map = M_DICT;
    for (int ci = 0; ci < 3; ci++) {
        bool ok = (n_in >= 24);
        for (int l = 0; l < 24 && ok; l++) ok = (in_sizes[cands[ci][l]] == ESZ[l]);
        if (ok) { map = cands[ci]; break; }
    }
#define INP(l) ((const float*)d_in[map[l]])
    const float* x     = INP(0);
    const float* mask  = INP(1);
    const float* eattr = INP(2);
    const int*   ei    = (const int*)d_in[map[3]];
    const float *m_w1 = INP(4), *m_b1 = INP(5), *m_w2 = INP(6), *m_b2 = INP(7);
    const float *ea0w1 = INP(8), *ea0b1 = INP(9), *ea0w2 = INP(10), *ea0b2 = INP(11);
    const float *tag0w = INP(12), *tag0b = INP(13);
    const float *ea1w1 = INP(14), *ea1b1 = INP(15), *ea1w2 = INP(16), *ea1b2 = INP(17);
    const float *tag1w = INP(18), *tag1b = INP(19);
    const float *ea2w1 = INP(20), *ea2b1 = INP(21), *ea2w2 = INP(22), *ea2b2 = INP(23);
#undef INP
    float* out = (float*)d_out;
    (void)out_size;

    const int GN32 = NNODE / 32;   // 625
    const int GN16 = NNODE / 16;   // 1250
    const int GE32 = NEDGE / 32;   // 5000

    static float* s_nb[5] = {nullptr, nullptr, nullptr, nullptr, nullptr};
    static float* s_msg[3] = {nullptr, nullptr, nullptr};
    static cudaStream_t s1 = nullptr, s2 = nullptr;
    static cudaEvent_t evFork = nullptr, evS1 = nullptr, evS2 = nullptr;
    static cudaEvent_t evT0 = nullptr, evC1 = nullptr;
    static cudaEvent_t evT1 = nullptr, evC2 = nullptr;
    if (!s_nb[0]) {
        void* p = nullptr;
        cudaGetSymbolAddress(&p, g_nb);
        for (int i = 0; i < 5; i++) s_nb[i] = (float*)p + (size_t)i * NNODE * HH;
        cudaGetSymbolAddress(&p, g_msg);
        for (int i = 0; i < 3; i++) s_msg[i] = (float*)p + (size_t)i * NEDGE * HH;
        cudaStreamCreateWithFlags(&s1, cudaStreamNonBlocking);
        cudaStreamCreateWithFlags(&s2, cudaStreamNonBlocking);
        cudaEventCreateWithFlags(&evFork, cudaEventDisableTiming);
        cudaEventCreateWithFlags(&evS1, cudaEventDisableTiming);
        cudaEventCreateWithFlags(&evS2, cudaEventDisableTiming);
        cudaEventCreateWithFlags(&evT0, cudaEventDisableTiming);
        cudaEventCreateWithFlags(&evC1, cudaEventDisableTiming);
        cudaEventCreateWithFlags(&evT1, cudaEventDisableTiming);
        cudaEventCreateWithFlags(&evC2, cudaEventDisableTiming);
    }

    // ---- fork: CSR build on main; node GEMMs on s1; layer-0 C GEMM on s2 ----
    cudaEventRecord(evFork, 0);
    cudaStreamWaitEvent(s1, evFork, 0);
    cudaStreamWaitEvent(s2, evFork, 0);

    k_zero<<<(NNODE + 255) / 256, 256>>>();
    k_hist<<<E2 / 256, 256>>>(ei);
    k_scan<<<1, 1024>>>();
    k_scatter<<<E2 / 256, 256>>>(ei);

    k_maskmlp<<<GN16, 128, 0, s1>>>(x, mask, m_w1, m_b1, m_w2, m_b2);
    k_mm2<16><<<dim3(GN32, 2), 128, 0, s1>>>(-3, nullptr, ea0w1, ea0b1, ea0w1 + 16 * HH);

    k_mm<16, 0, false><<<GE32, 128, 0, s2>>>(-1, eattr, s_msg[0], ea0w1 + 32 * HH, nullptr);

    cudaEventRecord(evS1, s1);
    cudaEventRecord(evS2, s2);
    cudaStreamWaitEvent(0, evS1, 0);
    cudaStreamWaitEvent(0, evS2, 0);

    // ---- EA0: fused agg + layer-2 -> nb3 ----
    k_agg_mm<true><<<GN32, 256>>>(0, s_nb[3], ea0w2, ea0b2);

    // ---- TAG0: 3 fused hop+lin kernels; C1 GEMM overlapped on s2 ----
    cudaEventRecord(evT0, 0);
    cudaStreamWaitEvent(s2, evT0, 0);
    k_mm<16, 0, false><<<GE32, 128, 0, s2>>>(-1, eattr, s_msg[1], ea1w1 + 256 * HH, nullptr);
    cudaEventRecord(evC1, s2);

    k_hop_mm<2, 0><<<GN32, 256>>>(3, 0, tag0w,               tag0b);   // nb4 = b + lin0 h0 + lin1 h1
    k_hop_mm<1, 1><<<GN32, 256>>>(0, 1, tag0w + 2 * HH * HH, nullptr); // nb4 += lin2 h2
    k_hop_mm<1, 2><<<GN32, 256>>>(1, -1, tag0w + 3 * HH * HH, nullptr); // nb4 = relu(nb4 + lin3 h3)

    // ---- EA1 (nb4 -> 128) -> nb3 ----
    k_mm2<128><<<dim3(GN32, 2), 128>>>(4, nullptr, ea1w1, ea1b1, ea1w1 + 128 * HH);
    cudaStreamWaitEvent(0, evC1, 0);
    k_agg_mm<true><<<GN32, 256>>>(1, s_nb[3], ea1w2, ea1b2);

    // ---- TAG1: C2 GEMM overlapped on s2 ----
    cudaEventRecord(evT1, 0);
    cudaStreamWaitEvent(s2, evT1, 0);
    k_mm<16, 0, false><<<GE32, 128, 0, s2>>>(-1, eattr, s_msg[2], ea2w1 + 256 * HH, nullptr);
    cudaEventRecord(evC2, s2);

    k_hop_mm<2, 0><<<GN32, 256>>>(3, 0, tag1w,               tag1b);
    k_hop_mm<1, 1><<<GN32, 256>>>(0, 1, tag1w + 2 * HH * HH, nullptr);
    k_hop_mm<1, 2><<<GN32, 256>>>(1, -1, tag1w + 3 * HH * HH, nullptr);

    // ---- EA2 (nb4 -> 16) -> d_out ----
    k_mm2<128><<<dim3(GN32, 2), 128>>>(4, nullptr, ea2w1, ea2b1, ea2w1 + 128 * HH);
    cudaStreamWaitEvent(0, evC2, 0);
    k_agg_out16<<<GN32, 256>>>(2, out, ea2w2, ea2b2);
}

// round 16
// speedup vs baseline: 1.3696x; 1.0088x over previous
#include <cuda_runtime.h>
#include <math.h>

#define NNODE 20000
#define NEDGE 160000
#define E2    320000
#define HH    128
#define NF    16
#define EF    16

// ---------------- device scratch (no allocations allowed) ----------------
__device__ int   g_deg[NNODE];
__device__ int   g_rowoff[NNODE];
__device__ int   g_cursor[NNODE];
__device__ float g_dis[NNODE];
__device__ int   g_csr_src[E2];
__device__ int   g_csr_ea[E2];                 // eattr index (0..NEDGE)
__device__ float g_h0[NNODE * NF];
__device__ float g_nb[5][NNODE * HH];          // node-feature buffers
__device__ float g_msg[3][(size_t)NEDGE * HH]; // per-unique-edge C buffers

__device__ __forceinline__ const float* sel_in(int s, const float* ext) {
    if (s >= 0) return g_nb[s];
    if (s == -3) return g_h0;
    return ext;
}

// ---------------- graph structure build ----------------
__global__ void k_zero() {
    int i = blockIdx.x * 256 + threadIdx.x;
    if (i < NNODE) g_deg[i] = 0;
}

__global__ void k_hist(const int* __restrict__ ei) {
    int e = blockIdx.x * 256 + threadIdx.x;
    if (e >= E2) return;
    int d = (e < NEDGE) ? ei[NEDGE + e] : ei[e - NEDGE];
    atomicAdd(&g_deg[d], 1);
}

// warp-shuffle block scan (single block, 1024 threads, 20 elems/thread)
__global__ void k_scan() {
    __shared__ int wsum[32];
    int t = threadIdx.x, lane = t & 31, wid = t >> 5;
    const int PER = 20;
    int base = t * PER;
    int s = 0;
#pragma unroll
    for (int i = 0; i < PER; i++) { int idx = base + i; if (idx < NNODE) s += g_deg[idx]; }
    int x = s;
#pragma unroll
    for (int off = 1; off < 32; off <<= 1) {
        int y = __shfl_up_sync(0xffffffffu, x, off);
        if (lane >= off) x += y;
    }
    if (lane == 31) wsum[wid] = x;
    __syncthreads();
    if (wid == 0) {
        int y = wsum[lane];
#pragma unroll
        for (int off = 1; off < 32; off <<= 1) {
            int z = __shfl_up_sync(0xffffffffu, y, off);
            if (lane >= off) y += z;
        }
        wsum[lane] = y;
    }
    __syncthreads();
    int run = x - s + (wid > 0 ? wsum[wid - 1] : 0);
#pragma unroll
    for (int i = 0; i < PER; i++) {
        int idx = base + i;
        if (idx < NNODE) {
            int v = g_deg[idx];
            g_rowoff[idx] = run;
            g_cursor[idx] = run;
            g_dis[idx] = (v > 0) ? rsqrtf((float)v) : 0.f;
            run += v;
        }
    }
}

__global__ void k_scatter(const int* __restrict__ ei) {
    int e = blockIdx.x * 256 + threadIdx.x;
    if (e >= E2) return;
    int srcv = ei[e];
    int d  = (e < NEDGE) ? ei[NEDGE + e] : ei[e - NEDGE];
    int ea = (e < NEDGE) ? e : e - NEDGE;
    int slot = atomicAdd(&g_cursor[d], 1);
    g_csr_src[slot] = srcv;
    g_csr_ea[slot]  = ea;
}

// ---------------- mask MLP + residual: g_h0 = mlp2(mask) + x ----------------
__global__ void __launch_bounds__(128) k_maskmlp(
    const float* __restrict__ x, const float* __restrict__ mask,
    const float* __restrict__ w1, const float* __restrict__ b1,
    const float* __restrict__ w2, const float* __restrict__ b2)
{
    constexpr int T = 16;
    __shared__ __align__(16) float sM[T * NF];
    __shared__ __align__(16) float sH[T * HH];
    int tid = threadIdx.x;
    int n0 = blockIdx.x * T;
    for (int o = tid; o < T * NF; o += 128) sM[o] = mask[n0 * NF + o];
    __syncthreads();

    float acc[T];
    float bj = b1[tid];
#pragma unroll
    for (int t = 0; t < T; t++) acc[t] = bj;
#pragma unroll
    for (int i = 0; i < NF; i += 4) {
        float wa = w1[(i + 0) * HH + tid], wb = w1[(i + 1) * HH + tid];
        float wc = w1[(i + 2) * HH + tid], wd = w1[(i + 3) * HH + tid];
#pragma unroll
        for (int t = 0; t < T; t++) {
            float4 v = *reinterpret_cast<const float4*>(&sM[t * NF + i]);
            acc[t] = fmaf(v.x, wa, acc[t]); acc[t] = fmaf(v.y, wb, acc[t]);
            acc[t] = fmaf(v.z, wc, acc[t]); acc[t] = fmaf(v.w, wd, acc[t]);
        }
    }
#pragma unroll
    for (int t = 0; t < T; t++) sH[t * HH + tid] = fmaxf(acc[t], 0.f);
    __syncthreads();

    for (int o = tid; o < T * NF; o += 128) {
        int t = o >> 4, c = o & 15;
        float v = b2[c];
#pragma unroll 1
        for (int k = 0; k < HH; k += 4) {
            float4 h = *reinterpret_cast<const float4*>(&sH[t * HH + k]);
            v = fmaf(h.x, w2[(k + 0) * NF + c], v);
            v = fmaf(h.y, w2[(k + 1) * NF + c], v);
            v = fmaf(h.z, w2[(k + 2) * NF + c], v);
            v = fmaf(h.w, w2[(k + 3) * NF + c], v);
        }
        g_h0[n0 * NF + o] = v + x[n0 * NF + o];
    }
}

// ---------------- GEMM: out[M,128] = op(in[M,K] @ W[K,128])  T=32 rows/block ----
template <int K, int BIASMODE, bool RELU>
__global__ void __launch_bounds__(128) k_mm(
    int insel, const float* __restrict__ in_ext,
    float* __restrict__ outp,
    const float* __restrict__ W, const float* __restrict__ bias)
{
    constexpr int T = 32;
    __shared__ __align__(16) float sIn[T * K];
    const float* in = sel_in(insel, in_ext);
    int tid = threadIdx.x;
    int j = tid;
    int n0 = blockIdx.x * T;

    const float4* gsrc = reinterpret_cast<const float4*>(in + (size_t)n0 * K);
    float4* ssrc = reinterpret_cast<float4*>(sIn);
    for (int o = tid; o < T * K / 4; o += 128) ssrc[o] = gsrc[o];
    __syncthreads();

    float acc[T];
    if (BIASMODE == 1) {
        float b = bias[j];
#pragma unroll
        for (int t = 0; t < T; t++) acc[t] = b;
    } else {
#pragma unroll
        for (int t = 0; t < T; t++) acc[t] = 0.f;
    }

#pragma unroll 1
    for (int k = 0; k < K; k += 4) {
        float wa = W[(k + 0) * HH + j], wb = W[(k + 1) * HH + j];
        float wc = W[(k + 2) * HH + j], wd = W[(k + 3) * HH + j];
#pragma unroll
        for (int t = 0; t < T; t++) {
            float4 v = *reinterpret_cast<const float4*>(&sIn[t * K + k]);
            acc[t] = fmaf(v.x, wa, acc[t]); acc[t] = fmaf(v.y, wb, acc[t]);
            acc[t] = fmaf(v.z, wc, acc[t]); acc[t] = fmaf(v.w, wd, acc[t]);
        }
    }

#pragma unroll
    for (int t = 0; t < T; t++) {
        float v = acc[t];
        if (RELU) v = fmaxf(v, 0.f);
        outp[(size_t)(n0 + t) * HH + j] = v;
    }
}

// ---------------- twin GEMM via gridDim.y (EA0 path) ----------------
template <int K>
__global__ void __launch_bounds__(128) k_mm2(
    int insel, const float* __restrict__ in_ext,
    const float* __restrict__ WA, const float* __restrict__ biasA,
    const float* __restrict__ WB)
{
    constexpr int T = 32;
    __shared__ __align__(16) float sIn[T * K];
    const float* in = sel_in(insel, in_ext);
    int tid = threadIdx.x;
    int j = tid;
    int n0 = blockIdx.x * T;
    bool isA = (blockIdx.y == 0);
    const float* W = isA ? WA : WB;
    float* outp = g_nb[isA ? 0 : 1];

    const float4* gsrc = reinterpret_cast<const float4*>(in + (size_t)n0 * K);
    float4* ssrc = reinterpret_cast<float4*>(sIn);
    for (int o = tid; o < T * K / 4; o += 128) ssrc[o] = gsrc[o];
    __syncthreads();

    float acc[T];
    float b = isA ? biasA[j] : 0.f;
#pragma unroll
    for (int t = 0; t < T; t++) acc[t] = b;

#pragma unroll 1
    for (int k = 0; k < K; k += 4) {
        float wa = W[(k + 0) * HH + j], wb = W[(k + 1) * HH + j];
        float wc = W[(k + 2) * HH + j], wd = W[(k + 3) * HH + j];
#pragma unroll
        for (int t = 0; t < T; t++) {
            float4 v = *reinterpret_cast<const float4*>(&sIn[t * K + k]);
            acc[t] = fmaf(v.x, wa, acc[t]); acc[t] = fmaf(v.y, wb, acc[t]);
            acc[t] = fmaf(v.z, wc, acc[t]); acc[t] = fmaf(v.w, wd, acc[t]);
        }
    }
#pragma unroll
    for (int t = 0; t < T; t++)
        outp[(size_t)(n0 + t) * HH + j] = acc[t];
}

// ---------------- fused TAG hop + lin GEMM (first/middle hops) ----------------
// NSEG==2: stages h_prev rows as segment 0; ACCMODE: 0=init bias, 1=accumulate.
template <int NSEG, int ACCMODE>
__global__ void __launch_bounds__(256) k_hop_mm(
    int insel, int outsel,
    const float* __restrict__ W, const float* __restrict__ bias)
{
    constexpr int T = 32;
    constexpr int K = NSEG * 128;
    __shared__ __align__(16) float sIn[T * K];
    const float4* __restrict__ hin4 = reinterpret_cast<const float4*>(g_nb[insel]);
    int tid = threadIdx.x, lane = tid & 31, wid = tid >> 5;
    int n0 = blockIdx.x * T;

    if (NSEG == 2) {
        const float4* src = hin4 + (size_t)n0 * 32;
        for (int o = tid; o < T * 32; o += 256) {
            int r = o >> 5, c = o & 31;
            *reinterpret_cast<float4*>(&sIn[r * K + c * 4]) = src[(size_t)r * 32 + c];
        }
    }

    const int cbase = (NSEG - 1) * 128;
    float4* houtg = (outsel >= 0) ? reinterpret_cast<float4*>(g_nb[outsel]) : nullptr;
    for (int u = 0; u < 4; u++) {
        int r = wid * 4 + u;
        int n = n0 + r;
        int beg = g_rowoff[n], len = g_deg[n];
        float4 acc = make_float4(0.f, 0.f, 0.f, 0.f);
        for (int i = 0; i < len; i++) {
            int s = __ldg(&g_csr_src[beg + i]);
            float d = __ldg(&g_dis[s]);
            float4 h = __ldg(&hin4[(size_t)s * 32 + lane]);
            acc.x = fmaf(d, h.x, acc.x);
            acc.y = fmaf(d, h.y, acc.y);
            acc.z = fmaf(d, h.z, acc.z);
            acc.w = fmaf(d, h.w, acc.w);
        }
        float dn = g_dis[n];
        acc.x *= dn; acc.y *= dn; acc.z *= dn; acc.w *= dn;
        *reinterpret_cast<float4*>(&sIn[r * K + cbase + lane * 4]) = acc;
        if (houtg) houtg[(size_t)n * 32 + lane] = acc;
    }
    __syncthreads();

    float* out = g_nb[4];
    int j = tid & 127;
    int g = tid >> 7;
    int tb = g * 16;
    float acc[16];
    if (ACCMODE == 0) {
        float b = bias[j];
#pragma unroll
        for (int t = 0; t < 16; t++) acc[t] = b;
    } else {
#pragma unroll
        for (int t = 0; t < 16; t++) acc[t] = out[(size_t)(n0 + tb + t) * HH + j];
    }

#pragma unroll 1
    for (int k = 0; k < K; k += 4) {
        float wa = W[(k + 0) * HH + j], wb = W[(k + 1) * HH + j];
        float wc = W[(k + 2) * HH + j], wd = W[(k + 3) * HH + j];
#pragma unroll
        for (int t = 0; t < 16; t++) {
            float4 v = *reinterpret_cast<const float4*>(&sIn[(tb + t) * K + k]);
            acc[t] = fmaf(v.x, wa, acc[t]); acc[t] = fmaf(v.y, wb, acc[t]);
            acc[t] = fmaf(v.z, wc, acc[t]); acc[t] = fmaf(v.w, wd, acc[t]);
        }
    }
#pragma unroll
    for (int t = 0; t < 16; t++)
        out[(size_t)(n0 + tb + t) * HH + j] = acc[t];
}

// ---------------- fused last hop + relu + EA A/B projections ----------------
// Gathers from g_nb[insel] (READ-ONLY for the whole kernel).
// t4 = relu(nb4 + hop@W3) in smem; A -> nb0, B -> nb2 (neither is a gather
// input of this kernel, so no cross-block race).
__global__ void __launch_bounds__(256) k_hop_mm_ab(
    int insel,
    const float* __restrict__ W3,
    const float* __restrict__ WA, const float* __restrict__ biasA,
    const float* __restrict__ WB)
{
    constexpr int T = 32;
    __shared__ __align__(16) float sG[T * HH];   // gathered h3
    __shared__ __align__(16) float sH[T * HH];   // t4
    const float4* __restrict__ hin4 = reinterpret_cast<const float4*>(g_nb[insel]);
    int tid = threadIdx.x, lane = tid & 31, wid = tid >> 5;
    int n0 = blockIdx.x * T;

    // phase 1: gather h3 -> sG
    for (int u = 0; u < 4; u++) {
        int r = wid * 4 + u;
        int n = n0 + r;
        int beg = g_rowoff[n], len = g_deg[n];
        float4 acc = make_float4(0.f, 0.f, 0.f, 0.f);
        for (int i = 0; i < len; i++) {
            int s = __ldg(&g_csr_src[beg + i]);
            float d = __ldg(&g_dis[s]);
            float4 h = __ldg(&hin4[(size_t)s * 32 + lane]);
            acc.x = fmaf(d, h.x, acc.x);
            acc.y = fmaf(d, h.y, acc.y);
            acc.z = fmaf(d, h.z, acc.z);
            acc.w = fmaf(d, h.w, acc.w);
        }
        float dn = g_dis[n];
        acc.x *= dn; acc.y *= dn; acc.z *= dn; acc.w *= dn;
        *reinterpret_cast<float4*>(&sG[r * HH + lane * 4]) = acc;
    }
    __syncthreads();

    // phase 2a: t4 = relu(nb4 + sG @ W3) -> sH (own rows of nb4 only)
    {
        const float* nb4 = g_nb[4];
        int j = tid & 127;
        int g = tid >> 7;
        int tb = g * 16;
        float acc[16];
#pragma unroll
        for (int t = 0; t < 16; t++) acc[t] = nb4[(size_t)(n0 + tb + t) * HH + j];
#pragma unroll 1
        for (int k = 0; k < HH; k += 4) {
            float wa = W3[(k + 0) * HH + j], wb = W3[(k + 1) * HH + j];
            float wc = W3[(k + 2) * HH + j], wd = W3[(k + 3) * HH + j];
#pragma unroll
            for (int t = 0; t < 16; t++) {
                float4 v = *reinterpret_cast<const float4*>(&sG[(tb + t) * HH + k]);
                acc[t] = fmaf(v.x, wa, acc[t]); acc[t] = fmaf(v.y, wb, acc[t]);
                acc[t] = fmaf(v.z, wc, acc[t]); acc[t] = fmaf(v.w, wd, acc[t]);
            }
        }
#pragma unroll
        for (int t = 0; t < 16; t++)
            sH[(tb + t) * HH + j] = fmaxf(acc[t], 0.f);
    }
    __syncthreads();

    // phase 2b: nb0 = sH@WA + bA (tid<128), nb2 = sH@WB (tid>=128)
    {
        int j = tid & 127;
        bool isA = tid < 128;
        const float* W = isA ? WA : WB;
        float* outp = g_nb[isA ? 0 : 2];
        float acc[T];
        float b = isA ? biasA[j] : 0.f;
#pragma unroll
        for (int t = 0; t < T; t++) acc[t] = b;
#pragma unroll 1
        for (int k = 0; k < HH; k += 4) {
            float wa = W[(k + 0) * HH + j], wb = W[(k + 1) * HH + j];
            float wc = W[(k + 2) * HH + j], wd = W[(k + 3) * HH + j];
#pragma unroll
            for (int t = 0; t < T; t++) {
                float4 v = *reinterpret_cast<const float4*>(&sH[t * HH + k]);
                acc[t] = fmaf(v.x, wa, acc[t]); acc[t] = fmaf(v.y, wb, acc[t]);
                acc[t] = fmaf(v.z, wc, acc[t]); acc[t] = fmaf(v.w, wd, acc[t]);
            }
        }
#pragma unroll
        for (int t = 0; t < T; t++)
            outp[(size_t)(n0 + t) * HH + j] = acc[t];
    }
}

// ---------------- fused agg + layer-2 GEMM (B buffer selectable) ----------------
template <bool RELU>
__global__ void __launch_bounds__(256) k_agg_mm(
    int msel, int bsel, float* __restrict__ outp,
    const float* __restrict__ W, const float* __restrict__ bias)
{
    constexpr int T = 32;
    __shared__ __align__(16) float sS[T * HH];
    const float4* __restrict__ A = reinterpret_cast<const float4*>(g_nb[0]);
    const float4* __restrict__ B = reinterpret_cast<const float4*>(g_nb[bsel]);
    const float4* __restrict__ M = reinterpret_cast<const float4*>(g_msg[msel]);
    int tid = threadIdx.x;
    int lane = tid & 31, wid = tid >> 5;
    int n0 = blockIdx.x * T;

    for (int u = 0; u < 4; u++) {
        int r = wid * 4 + u;
        int n = n0 + r;
        int beg = g_rowoff[n], len = g_deg[n];
        float4 a = A[(size_t)n * 32 + lane];
        float4 acc = make_float4(0.f, 0.f, 0.f, 0.f);
        for (int i = 0; i < len; i++) {
            int s  = __ldg(&g_csr_src[beg + i]);
            int ea = __ldg(&g_csr_ea[beg + i]);
            float4 b = __ldg(&B[(size_t)s * 32 + lane]);
            float4 m = __ldg(&M[(size_t)ea * 32 + lane]);
            acc.x += fmaxf(a.x + b.x + m.x, 0.f);
            acc.y += fmaxf(a.y + b.y + m.y, 0.f);
            acc.z += fmaxf(a.z + b.z + m.z, 0.f);
            acc.w += fmaxf(a.w + b.w + m.w, 0.f);
        }
        *reinterpret_cast<float4*>(&sS[r * HH + lane * 4]) = acc;
    }
    __syncthreads();

    int j = tid & 127;
    int g = tid >> 7;
    int tbase = g * 16;
    float acc[16];
    float bj = bias[j];
#pragma unroll
    for (int t = 0; t < 16; t++) acc[t] = bj * (float)g_deg[n0 + tbase + t];

#pragma unroll 1
    for (int k = 0; k < HH; k += 4) {
        float wa = W[(k + 0) * HH + j], wb = W[(k + 1) * HH + j];
        float wc = W[(k + 2) * HH + j], wd = W[(k + 3) * HH + j];
#pragma unroll
        for (int t = 0; t < 16; t++) {
            float4 v = *reinterpret_cast<const float4*>(&sS[(tbase + t) * HH + k]);
            acc[t] = fmaf(v.x, wa, acc[t]); acc[t] = fmaf(v.y, wb, acc[t]);
            acc[t] = fmaf(v.z, wc, acc[t]); acc[t] = fmaf(v.w, wd, acc[t]);
        }
    }
#pragma unroll
    for (int t = 0; t < 16; t++) {
        float v = acc[t];
        if (RELU) v = fmaxf(v, 0.f);
        outp[(size_t)(n0 + tbase + t) * HH + j] = v;
    }
}

// ---------------- fused agg + final 16-col GEMM -> d_out ----------------
__global__ void __launch_bounds__(256) k_agg_out16(
    int msel, int bsel, float* __restrict__ out,
    const float* __restrict__ W2, const float* __restrict__ b2)
{
    constexpr int T = 32;
    __shared__ __align__(16) float sS[T * HH];
    const float4* __restrict__ A = reinterpret_cast<const float4*>(g_nb[0]);
    const float4* __restrict__ B = reinterpret_cast<const float4*>(g_nb[bsel]);
    const float4* __restrict__ M = reinterpret_cast<const float4*>(g_msg[msel]);
    int tid = threadIdx.x;
    int lane = tid & 31, wid = tid >> 5;
    int n0 = blockIdx.x * T;

    for (int u = 0; u < 4; u++) {
        int r = wid * 4 + u;
        int n = n0 + r;
        int beg = g_rowoff[n], len = g_deg[n];
        float4 a = A[(size_t)n * 32 + lane];
        float4 acc = make_float4(0.f, 0.f, 0.f, 0.f);
        for (int i = 0; i < len; i++) {
            int s  = __ldg(&g_csr_src[beg + i]);
            int ea = __ldg(&g_csr_ea[beg + i]);
            float4 b = __ldg(&B[(size_t)s * 32 + lane]);
            float4 m = __ldg(&M[(size_t)ea * 32 + lane]);
            acc.x += fmaxf(a.x + b.x + m.x, 0.f);
            acc.y += fmaxf(a.y + b.y + m.y, 0.f);
            acc.z += fmaxf(a.z + b.z + m.z, 0.f);
            acc.w += fmaxf(a.w + b.w + m.w, 0.f);
        }
        *reinterpret_cast<float4*>(&sS[r * HH + lane * 4]) = acc;
    }
    __syncthreads();

    int row = tid >> 3;
    int c0 = (tid & 7) * 2;
    int n = n0 + row;
    float dg = (float)g_deg[n];
    float a0 = b2[c0] * dg, a1 = b2[c0 + 1] * dg;
#pragma unroll 4
    for (int k = 0; k < HH; k++) {
        float s = sS[row * HH + k];
        a0 = fmaf(s, __ldg(&W2[k * 16 + c0]), a0);
        a1 = fmaf(s, __ldg(&W2[k * 16 + c0 + 1]), a1);
    }
    out[n * 16 + c0] = a0;
    out[n * 16 + c0 + 1] = a1;
}

// ---------------- launch ----------------
extern "C" void kernel_launch(void* const* d_in, const int* in_sizes, int n_in,
                              void* d_out, int out_size)
{
    static const int ESZ[24] = {
        320000, 320000, 2560000, 320000,
        2048, 128, 2048, 16,
        6144, 128, 16384, 128,
        65536, 128,
        34816, 128, 16384, 128,
        65536, 128,
        34816, 128, 2048, 16};
    static const int M_DICT[24] = {0,1,2,3,4,5,6,7,8,9,10,11,12,13,14,15,16,17,18,19,20,21,22,23};
    static const int M_SIG[24]  = {0,1,2,23,3,4,5,6,7,8,9,10,11,12,13,14,15,16,17,18,19,20,21,22};
    static const int M_ALPHA[24]= {23,18,12,13,16,14,17,15,2,0,3,1,20,19,6,4,7,5,22,21,10,8,11,9};
    const int* cands[3] = {M_DICT, M_SIG, M_ALPHA};
    const int* map = M_DICT;
    for (int ci = 0; ci < 3; ci++) {
        bool ok = (n_in >= 24);
        for (int l = 0; l < 24 && ok; l++) ok = (in_sizes[cands[ci][l]] == ESZ[l]);
        if (ok) { map = cands[ci]; break; }
    }
#define INP(l) ((const float*)d_in[map[l]])
    const float* x     = INP(0);
    const float* mask  = INP(1);
    const float* eattr = INP(2);
    const int*   ei    = (const int*)d_in[map[3]];
    const float *m_w1 = INP(4), *m_b1 = INP(5), *m_w2 = INP(6), *m_b2 = INP(7);
    const float *ea0w1 = INP(8), *ea0b1 = INP(9), *ea0w2 = INP(10), *ea0b2 = INP(11);
    const float *tag0w = INP(12), *tag0b = INP(13);
    const float *ea1w1 = INP(14), *ea1b1 = INP(15), *ea1w2 = INP(16), *ea1b2 = INP(17);
    const float *tag1w = INP(18), *tag1b = INP(19);
    const float *ea2w1 = INP(20), *ea2b1 = INP(21), *ea2w2 = INP(22), *ea2b2 = INP(23);
#undef INP
    float* out = (float*)d_out;
    (void)out_size;

    const int GN32 = NNODE / 32;   // 625
    const int GN16 = NNODE / 16;   // 1250
    const int GE32 = NEDGE / 32;   // 5000

    static float* s_nb[5] = {nullptr, nullptr, nullptr, nullptr, nullptr};
    static float* s_msg[3] = {nullptr, nullptr, nullptr};
    static cudaStream_t s1 = nullptr, s2 = nullptr;
    static cudaEvent_t evFork = nullptr, evS1 = nullptr, evS2 = nullptr;
    static cudaEvent_t evT0 = nullptr, evC1 = nullptr;
    static cudaEvent_t evT1 = nullptr, evC2 = nullptr;
    if (!s_nb[0]) {
        void* p = nullptr;
        cudaGetSymbolAddress(&p, g_nb);
        for (int i = 0; i < 5; i++) s_nb[i] = (float*)p + (size_t)i * NNODE * HH;
        cudaGetSymbolAddress(&p, g_msg);
        for (int i = 0; i < 3; i++) s_msg[i] = (float*)p + (size_t)i * NEDGE * HH;
        cudaStreamCreateWithFlags(&s1, cudaStreamNonBlocking);
        cudaStreamCreateWithFlags(&s2, cudaStreamNonBlocking);
        cudaEventCreateWithFlags(&evFork, cudaEventDisableTiming);
        cudaEventCreateWithFlags(&evS1, cudaEventDisableTiming);
        cudaEventCreateWithFlags(&evS2, cudaEventDisableTiming);
        cudaEventCreateWithFlags(&evT0, cudaEventDisableTiming);
        cudaEventCreateWithFlags(&evC1, cudaEventDisableTiming);
        cudaEventCreateWithFlags(&evT1, cudaEventDisableTiming);
        cudaEventCreateWithFlags(&evC2, cudaEventDisableTiming);
    }

    // ---- fork: CSR build on main; node GEMMs on s1; layer-0 C GEMM on s2 ----
    cudaEventRecord(evFork, 0);
    cudaStreamWaitEvent(s1, evFork, 0);
    cudaStreamWaitEvent(s2, evFork, 0);

    k_zero<<<(NNODE + 255) / 256, 256>>>();
    k_hist<<<E2 / 256, 256>>>(ei);
    k_scan<<<1, 1024>>>();
    k_scatter<<<E2 / 256, 256>>>(ei);

    k_maskmlp<<<GN16, 128, 0, s1>>>(x, mask, m_w1, m_b1, m_w2, m_b2);
    k_mm2<16><<<dim3(GN32, 2), 128, 0, s1>>>(-3, nullptr, ea0w1, ea0b1, ea0w1 + 16 * HH);

    k_mm<16, 0, false><<<GE32, 128, 0, s2>>>(-1, eattr, s_msg[0], ea0w1 + 32 * HH, nullptr);

    cudaEventRecord(evS1, s1);
    cudaEventRecord(evS2, s2);
    cudaStreamWaitEvent(0, evS1, 0);
    cudaStreamWaitEvent(0, evS2, 0);

    // ---- EA0: fused agg + layer-2 -> nb3 (A=nb0, B=nb1) ----
    k_agg_mm<true><<<GN32, 256>>>(0, 1, s_nb[3], ea0w2, ea0b2);

    // ---- TAG0 + EA1 projections; C1 GEMM overlapped on s2 ----
    cudaEventRecord(evT0, 0);
    cudaStreamWaitEvent(s2, evT0, 0);
    k_mm<16, 0, false><<<GE32, 128, 0, s2>>>(-1, eattr, s_msg[1], ea1w1 + 256 * HH, nullptr);
    cudaEventRecord(evC1, s2);

    k_hop_mm<2, 0><<<GN32, 256>>>(3, 0, tag0w,               tag0b);   // nb4 = b + lin0 h0 + lin1 h1
    k_hop_mm<1, 1><<<GN32, 256>>>(0, 1, tag0w + 2 * HH * HH, nullptr); // nb4 += lin2 h2
    k_hop_mm_ab<<<GN32, 256>>>(1, tag0w + 3 * HH * HH,
                               ea1w1, ea1b1, ea1w1 + 128 * HH);        // A->nb0, B->nb2

    cudaStreamWaitEvent(0, evC1, 0);
    k_agg_mm<true><<<GN32, 256>>>(1, 2, s_nb[3], ea1w2, ea1b2);        // B=nb2

    // ---- TAG1 + EA2 projections; C2 GEMM overlapped on s2 ----
    cudaEventRecord(evT1, 0);
    cudaStreamWaitEvent(s2, evT1, 0);
    k_mm<16, 0, false><<<GE32, 128, 0, s2>>>(-1, eattr, s_msg[2], ea2w1 + 256 * HH, nullptr);
    cudaEventRecord(evC2, s2);

    k_hop_mm<2, 0><<<GN32, 256>>>(3, 0, tag1w,               tag1b);
    k_hop_mm<1, 1><<<GN32, 256>>>(0, 1, tag1w + 2 * HH * HH, nullptr);
    k_hop_mm_ab<<<GN32, 256>>>(1, tag1w + 3 * HH * HH,
                               ea2w1, ea2b1, ea2w1 + 128 * HH);        // A->nb0, B->nb2

    cudaStreamWaitEvent(0, evC2, 0);
    k_agg_out16<<<GN32, 256>>>(2, 2, out, ea2w2, ea2b2);               // B=nb2
}